// round 6
// baseline (speedup 1.0000x reference)
#include <cuda_runtime.h>
#include <cuda_fp16.h>
#include <cstdint>

// ---------------------------------------------------------------------------
// Problem: B=16, T=64, N=49(+1)=50 nodes, D=H=512, WIN=7
// ---------------------------------------------------------------------------
#define NEGBIG (-1e9f)

static const long long OUT_ELEMS  = 51200LL * 512;
static const long long ATTN_ELEMS = 1024LL * 2500;
static const long long COS_ELEMS  = 50400LL;

// ---------------------------------------------------------------------------
// Device scratch
// ---------------------------------------------------------------------------
__device__ float  g_node[51200 * 512];
__device__ float  g_spatial[51200 * 512];
__device__ float  g_t1[51200 * 512];
__device__ float  g_t2[51200 * 512];
__device__ float  g_attn[1024 * 2500];
__device__ float  g_cos[50400];
__device__ __half g_hA[51200 * 512];     // concat out (half)
__device__ __half g_hc[50400 * 512];     // cos*prev
__device__ __half g_hs[50400 * 512];     // (1-cos)*cur
__device__ __half g_ht3[51200 * 512];    // ln(out_pre)
__device__ __half g_hnode[51200 * 512];  // node (half mirror)
__device__ __half g_wh[8 * 512 * 512];   // half weights

// ---------------------------------------------------------------------------
// helpers
// ---------------------------------------------------------------------------
__device__ __forceinline__ uint32_t smem_u32(const void* p) {
    uint32_t a;
    asm("{ .reg .u64 t; cvta.to.shared.u64 t, %1; cvt.u32.u64 %0, t; }"
        : "=r"(a) : "l"(p));
    return a;
}
__device__ __forceinline__ uint32_t sw128(uint32_t off) {
    return off ^ ((off >> 3) & 0x70);
}
__device__ __forceinline__ void cp16(uint32_t dst, const void* src) {
    asm volatile("cp.async.cg.shared.global [%0], [%1], 16;\n"
                 :: "r"(dst), "l"(src));
}
__device__ __forceinline__ void cp_commit() {
    asm volatile("cp.async.commit_group;\n" ::: "memory");
}
__device__ __forceinline__ void cp_wait1() {
    asm volatile("cp.async.wait_group 1;\n" ::: "memory");
}
__device__ __forceinline__ void ldm_x4(uint32_t r[4], uint32_t addr) {
    asm volatile("ldmatrix.sync.aligned.m8n8.x4.shared.b16 {%0,%1,%2,%3}, [%4];"
                 : "=r"(r[0]), "=r"(r[1]), "=r"(r[2]), "=r"(r[3]) : "r"(addr));
}
__device__ __forceinline__ void mma_fp16(
    float c[4], uint32_t a0, uint32_t a1, uint32_t a2, uint32_t a3,
    uint32_t b0, uint32_t b1)
{
    asm volatile(
        "mma.sync.aligned.m16n8k16.row.col.f32.f16.f16.f32 "
        "{%0,%1,%2,%3}, {%4,%5,%6,%7}, {%8,%9}, {%0,%1,%2,%3};\n"
        : "+f"(c[0]), "+f"(c[1]), "+f"(c[2]), "+f"(c[3])
        : "r"(a0), "r"(a1), "r"(a2), "r"(a3), "r"(b0), "r"(b1));
}

// ---------------------------------------------------------------------------
// weights -> half, two 512x512 weights per launch (grid 512)
// ---------------------------------------------------------------------------
__global__ __launch_bounds__(256) void wround2_kernel(
    const float* __restrict__ s0, const float* __restrict__ s1,
    __half* __restrict__ d0, __half* __restrict__ d1)
{
    const float* s = (blockIdx.x < 256) ? s0 : s1;
    __half2* d = (__half2*)((blockIdx.x < 256) ? d0 : d1);
    int i = (blockIdx.x & 255) * 256 + threadIdx.x;
    float4 v = ((const float4*)s)[i];
    d[i * 2 + 0] = __floats2half2_rn(v.x, v.y);
    d[i * 2 + 1] = __floats2half2_rn(v.z, v.w);
}

// ---------------------------------------------------------------------------
// concat(visual, audio) -> half [51200, 512]
// ---------------------------------------------------------------------------
__global__ __launch_bounds__(256) void concat_kernel(
    const float* __restrict__ vis, const float* __restrict__ aud,
    __half* __restrict__ out)
{
    long long idx = (long long)blockIdx.x * 256 + threadIdx.x;
    if (idx >= (long long)51200 * 128) return;
    long long r = idx >> 7;
    int hv = (int)(idx & 127);
    int bt = (int)(r / 50), i = (int)(r % 50);
    float4 v;
    if (i < 49)
        v = ((const float4*)vis)[((long long)bt * 49 + i) * 128 + hv];
    else
        v = ((const float4*)aud)[(long long)bt * 128 + hv];
    __half2* d = (__half2*)out;
    d[idx * 2 + 0] = __floats2half2_rn(v.x, v.y);
    d[idx * 2 + 1] = __floats2half2_rn(v.z, v.w);
}

// ---------------------------------------------------------------------------
// fp16 tensor-core NT GEMM: C = epilogue(A[M,512] @ W[512,512]^T)
// CTA tile 256(M)x128(N), 512 threads / 16 warps (4x4), warp tile 64x32,
// k-tile 64, 3-stage cp.async pipeline, ldmatrix fragments.
// ---------------------------------------------------------------------------
#define STAGE_BYTES 49152          // A 256*128B + B 128*128B
#define GEMM_SMEM   (3 * STAGE_BYTES)

__global__ __launch_bounds__(512, 1) void gemm_fp16(
    const __half* __restrict__ A, const __half* __restrict__ W,
    const float* __restrict__ bias, const float* __restrict__ add1,
    const float* __restrict__ add2, float* __restrict__ C,
    __half* __restrict__ Ch, int M, int mode)
{
    extern __shared__ char smem[];
    const uint32_t sb = smem_u32(smem);

    const int tid = threadIdx.x;
    const int wid = tid >> 5, lane = tid & 31;
    const int wm = wid >> 2, wn = wid & 3;          // 4x4 warp grid
    const int g = lane >> 2, t = lane & 3;
    const int m0 = blockIdx.y * 256;
    const int n0 = blockIdx.x * 128;

    float acc[4][4][4];
#pragma unroll
    for (int mf = 0; mf < 4; mf++)
#pragma unroll
        for (int nf = 0; nf < 4; nf++)
#pragma unroll
            for (int q = 0; q < 4; q++) acc[mf][nf][q] = 0.f;

    auto load_stage = [&](int s) {
        const int buf = s % 3;
        const uint32_t ab = sb + buf * STAGE_BYTES;   // A: 256 rows * 128B
        const uint32_t bb = ab + 32768;               // B: 128 rows * 128B
        const int k0 = s * 64;
#pragma unroll
        for (int i = 0; i < 6; i++) {
            int o = tid + i * 512;                    // 0..3071
            if (o < 2048) {
                int row = o >> 3, c = o & 7;
                uint32_t off = sw128((uint32_t)(row * 128 + c * 16));
                int sr = m0 + row; if (sr > M - 1) sr = M - 1;
                cp16(ab + off, A + (long long)sr * 512 + k0 + c * 8);
            } else {
                int oo = o - 2048;
                int row = oo >> 3, c = oo & 7;
                uint32_t off = sw128((uint32_t)(row * 128 + c * 16));
                cp16(bb + off, W + (long long)(n0 + row) * 512 + k0 + c * 8);
            }
        }
    };

    load_stage(0); cp_commit();
    load_stage(1); cp_commit();

    const int a_row = (lane & 15);
    const int a_c16 = (lane >> 4);
    const int b_row = ((lane >> 4) << 3) + (lane & 7);
    const int b_c16 = ((lane >> 3) & 1);

    for (int s = 0; s < 8; s++) {
        cp_wait1();
        __syncthreads();
        const int buf = s % 3;
        const uint32_t ab = sb + buf * STAGE_BYTES;
        const uint32_t bb = ab + 32768;

#pragma unroll
        for (int ks = 0; ks < 4; ks++) {
            uint32_t af[4][4], bf[2][4];
#pragma unroll
            for (int mf = 0; mf < 4; mf++) {
                int m = wm * 64 + mf * 16 + a_row;
                ldm_x4(af[mf], ab + sw128((uint32_t)(m * 128 + ks * 32 + a_c16 * 16)));
            }
#pragma unroll
            for (int np = 0; np < 2; np++) {
                int n = wn * 32 + np * 16 + b_row;
                ldm_x4(bf[np], bb + sw128((uint32_t)(n * 128 + ks * 32 + b_c16 * 16)));
            }
#pragma unroll
            for (int mf = 0; mf < 4; mf++) {
                mma_fp16(acc[mf][0], af[mf][0], af[mf][1], af[mf][2], af[mf][3],
                         bf[0][0], bf[0][1]);
                mma_fp16(acc[mf][1], af[mf][0], af[mf][1], af[mf][2], af[mf][3],
                         bf[0][2], bf[0][3]);
                mma_fp16(acc[mf][2], af[mf][0], af[mf][1], af[mf][2], af[mf][3],
                         bf[1][0], bf[1][1]);
                mma_fp16(acc[mf][3], af[mf][0], af[mf][1], af[mf][2], af[mf][3],
                         bf[1][2], bf[1][3]);
            }
        }
        if (s + 2 < 8) load_stage(s + 2);
        cp_commit();
    }

    // ---------------- epilogue ----------------
#pragma unroll
    for (int mf = 0; mf < 4; mf++) {
#pragma unroll
        for (int h = 0; h < 2; h++) {
            int m = m0 + wm * 64 + mf * 16 + g + h * 8;
            if (m >= M) continue;
            long long orow;
            if (mode == 2) {
                int b_ = m / 3150, tq = (m / 50) % 63, i_ = m % 50;
                orow = ((long long)(b_ * 64 + tq + 1) * 50 + i_) * 512;
            } else {
                orow = (long long)m * 512;
            }
            long long arow = (long long)m * 512;
#pragma unroll
            for (int nf = 0; nf < 4; nf++) {
                int n = n0 + wn * 32 + nf * 8 + t * 2;
                float v0 = acc[mf][nf][h * 2 + 0];
                float v1 = acc[mf][nf][h * 2 + 1];
                float o0, o1;
                if (mode == 0) {
                    o0 = v0 + bias[n]; o1 = v1 + bias[n + 1];
                } else if (mode == 1) {
                    o0 = fmaxf(v0 + bias[n], 0.f);
                    o1 = fmaxf(v1 + bias[n + 1], 0.f);
                } else if (mode == 2) {
                    o0 = add2[orow + n]     + add1[arow + n]     + fmaxf(v0 + bias[n], 0.f);
                    o1 = add2[orow + n + 1] + add1[arow + n + 1] + fmaxf(v1 + bias[n + 1], 0.f);
                } else {
                    o0 = add1[arow + n]     + fmaxf(v0, 0.f);
                    o1 = add1[arow + n + 1] + fmaxf(v1, 0.f);
                }
                *(float2*)(C + orow + n) = make_float2(o0, o1);
                if (mode == 3)
                    *(__half2*)(Ch + orow + n) = __floats2half2_rn(o0, o1);
            }
        }
    }
}

// ---------------------------------------------------------------------------
// Fused attention for one (b,t), 512 threads: Gram trick + softmax + agg
// ---------------------------------------------------------------------------
#define ATTN_SMEM_FLOATS (52*512 + 3*512 + 52*52 + 6*52 + 8)

__global__ __launch_bounds__(512) void attn_kernel(
    const float* __restrict__ x, const float* __restrict__ edge,
    float* __restrict__ y_out, float* __restrict__ attn_out)
{
    extern __shared__ float sm[];
    float* xs  = sm;               // [52][512], rows 50/51 zero
    float* es  = xs + 52 * 512;    // [3][512]
    float* G   = es + 3 * 512;     // [52][52]
    float* rq  = G + 52 * 52;
    float* rk0 = rq + 52;
    float* rk1 = rk0 + 52;
    float* d0  = rk1 + 52;
    float* d1  = d0 + 52;
    float* d2  = d1 + 52;
    float* sc  = d2 + 52;

    const int bt = blockIdx.x;
    const int tid = threadIdx.x;
    const float* xg = x + (long long)bt * 50 * 512;

    for (int idx = tid; idx < 50 * 128; idx += 512)
        ((float4*)xs)[idx] = ((const float4*)xg)[idx];
    for (int idx = tid; idx < 2 * 128; idx += 512)
        ((float4*)xs)[50 * 128 + idx] = make_float4(0.f, 0.f, 0.f, 0.f);
    for (int idx = tid; idx < 3 * 128; idx += 512)
        ((float4*)es)[idx] = ((const float4*)edge)[idx];
    __syncthreads();

    if (tid < 338) {
        int i0 = (tid / 26) * 4, j0 = (tid % 26) * 2;
        float acc[4][2];
#pragma unroll
        for (int u = 0; u < 4; u++)
#pragma unroll
            for (int v = 0; v < 2; v++) acc[u][v] = 0.f;
        const float4* xi0 = (const float4*)(xs + (i0 + 0) * 512);
        const float4* xi1 = (const float4*)(xs + (i0 + 1) * 512);
        const float4* xi2 = (const float4*)(xs + (i0 + 2) * 512);
        const float4* xi3 = (const float4*)(xs + (i0 + 3) * 512);
        const float4* xj0 = (const float4*)(xs + (j0 + 0) * 512);
        const float4* xj1 = (const float4*)(xs + (j0 + 1) * 512);
#pragma unroll 4
        for (int k = 0; k < 128; k++) {
            float4 A0 = xi0[k], A1 = xi1[k], A2 = xi2[k], A3 = xi3[k];
            float4 B0 = xj0[k], B1 = xj1[k];
#define GACC(u,v,Au,Bv) acc[u][v] += Au.x*Bv.x + Au.y*Bv.y + Au.z*Bv.z + Au.w*Bv.w;
            GACC(0,0,A0,B0) GACC(0,1,A0,B1)
            GACC(1,0,A1,B0) GACC(1,1,A1,B1)
            GACC(2,0,A2,B0) GACC(2,1,A2,B1)
            GACC(3,0,A3,B0) GACC(3,1,A3,B1)
#undef GACC
        }
#pragma unroll
        for (int u = 0; u < 4; u++)
#pragma unroll
            for (int v = 0; v < 2; v++)
                G[(i0 + u) * 52 + (j0 + v)] = acc[u][v];
    }
    __syncthreads();

    if (tid < 150) {
        int kk = tid % 3, i = tid / 3;
        const float4* ev = (const float4*)(es + kk * 512);
        const float4* xv = (const float4*)(xs + i * 512);
        float s = 0.f;
        for (int k = 0; k < 128; k++) {
            float4 e4 = ev[k], x4 = xv[k];
            s += e4.x * x4.x + e4.y * x4.y + e4.z * x4.z + e4.w * x4.w;
        }
        (kk == 0 ? d0 : (kk == 1 ? d1 : d2))[i] = s;
    } else if (tid >= 160 && tid < 163) {
        int kk = tid - 160;
        const float4* ev = (const float4*)(es + kk * 512);
        float s = 0.f;
        for (int k = 0; k < 128; k++) {
            float4 e4 = ev[k];
            s += e4.x * e4.x + e4.y * e4.y + e4.z * e4.z + e4.w * e4.w;
        }
        sc[kk] = s;
    }
    __syncthreads();

    if (tid < 50) {
        float gd = G[tid * 53];
        rq[tid]  = 1.f / fmaxf(sqrtf(gd), 1e-12f);
        rk0[tid] = 1.f / fmaxf(sqrtf(gd + 2.f * d0[tid] + sc[0]), 1e-12f);
        rk1[tid] = 1.f / fmaxf(sqrtf(gd + 2.f * d1[tid] + sc[1]), 1e-12f);
    } else if (tid == 50) {
        sc[3] = 1.f / fmaxf(sqrtf(G[49 * 53] + 2.f * d2[49] + sc[2]), 1e-12f);
    }
    __syncthreads();

    const float rk2  = sc[3];
    const float d149 = d1[49];
    const float rq49 = rq[49];

    for (int p = tid; p < 2500; p += 512) {
        int i = p / 50, j = p - i * 50;
        float v;
        if (i == j)        v = NEGBIG;
        else if (j == 49)  v = (G[i * 52 + 49] + d2[i]) * rq[i] * rk2;
        else if (i == 49)  v = (G[49 * 52 + j] + d149) * rq49 * rk1[j];
        else {
            int qr = i / 7, qc = i - qr * 7;
            int kr = j / 7, kc = j - kr * 7;
            int r0 = qr - 1; if (r0 < 0) r0 = 0;
            int c0 = qc - 1; if (c0 < 0) c0 = 0; if (c0 > 4) c0 = 4;
            bool ok = (kr >= r0) && (kr <= r0 + 2) && (kc >= c0) && (kc <= c0 + 2);
            v = ok ? (G[i * 52 + j] + d0[i]) * rq[i] * rk0[j] : NEGBIG;
        }
        G[i * 52 + j] = v;
    }
    __syncthreads();

    if (tid < 50) {
        float* row = G + tid * 52;
        float mx = -3.4e38f;
        for (int j = 0; j < 50; j++) mx = fmaxf(mx, row[j]);
        float s = 0.f;
        for (int j = 0; j < 50; j++) { float e = expf(row[j] - mx); row[j] = e; s += e; }
        float inv = 1.f / s;
        for (int j = 0; j < 50; j++) row[j] *= inv;
    }
    __syncthreads();

    for (int p = tid; p < 2500; p += 512)
        attn_out[(long long)bt * 2500 + p] = G[(p / 50) * 52 + (p % 50)];

    for (int w = tid; w < 13 * 128; w += 512) {
        int it = w >> 7, hv = w & 127;
        int i0 = it * 4;
        float4 acc[4];
#pragma unroll
        for (int u = 0; u < 4; u++) acc[u] = make_float4(0.f, 0.f, 0.f, 0.f);
        for (int j = 0; j < 50; j++) {
            float4 xv = ((const float4*)(xs + j * 512))[hv];
            float a0 = G[(i0 + 0) * 52 + j];
            float a1 = G[(i0 + 1) * 52 + j];
            float a2 = G[(i0 + 2) * 52 + j];
            float a3 = G[(i0 + 3) * 52 + j];
            acc[0].x += a0 * xv.x; acc[0].y += a0 * xv.y; acc[0].z += a0 * xv.z; acc[0].w += a0 * xv.w;
            acc[1].x += a1 * xv.x; acc[1].y += a1 * xv.y; acc[1].z += a1 * xv.z; acc[1].w += a1 * xv.w;
            acc[2].x += a2 * xv.x; acc[2].y += a2 * xv.y; acc[2].z += a2 * xv.z; acc[2].w += a2 * xv.w;
            acc[3].x += a3 * xv.x; acc[3].y += a3 * xv.y; acc[3].z += a3 * xv.z; acc[3].w += a3 * xv.w;
        }
        float4 e2v = ((const float4*)(es + 1024))[hv];
#pragma unroll
        for (int u = 0; u < 4; u++) {
            int i = i0 + u;
            if (i >= 50) break;
            float aL = G[i * 52 + 49];
            float4 esel = ((const float4*)(es + (i < 49 ? 0 : 512)))[hv];
            float4 xr = ((const float4*)(xs + i * 512))[hv];
            float w1 = 1.f - aL;
            float4 o;
            o.x = acc[u].x + w1 * esel.x + aL * e2v.x + xr.x;
            o.y = acc[u].y + w1 * esel.y + aL * e2v.y + xr.y;
            o.z = acc[u].z + w1 * esel.z + aL * e2v.z + xr.z;
            o.w = acc[u].w + w1 * esel.w + aL * e2v.w + xr.w;
            ((float4*)(y_out + ((long long)bt * 50 + i) * 512))[hv] = o;
        }
    }
}

// ---------------------------------------------------------------------------
// LayerNorm (warp per 512-row); writes fp32 (if outf) and/or half (if outh)
// ---------------------------------------------------------------------------
__global__ __launch_bounds__(256) void ln_kernel(
    const float* __restrict__ in, float* __restrict__ outf,
    __half* __restrict__ outh,
    const float* __restrict__ g, const float* __restrict__ b,
    int rows, int do_relu)
{
    int warp = (blockIdx.x * 256 + threadIdx.x) >> 5;
    int lane = threadIdx.x & 31;
    if (warp >= rows) return;
    const float4* ip = (const float4*)(in + (long long)warp * 512);
    float4 v[4];
    float s = 0.f;
#pragma unroll
    for (int q = 0; q < 4; q++) {
        v[q] = ip[lane + 32 * q];
        s += v[q].x + v[q].y + v[q].z + v[q].w;
    }
#pragma unroll
    for (int off = 16; off; off >>= 1) s += __shfl_xor_sync(0xffffffffu, s, off);
    float mean = s * (1.f / 512.f);
    float ss = 0.f;
#pragma unroll
    for (int q = 0; q < 4; q++) {
        float dx = v[q].x - mean, dy = v[q].y - mean, dz = v[q].z - mean, dw = v[q].w - mean;
        ss += dx * dx + dy * dy + dz * dz + dw * dw;
    }
#pragma unroll
    for (int off = 16; off; off >>= 1) ss += __shfl_xor_sync(0xffffffffu, ss, off);
    float inv = rsqrtf(ss * (1.f / 512.f) + 1e-5f);
    const float4* gp = (const float4*)g;
    const float4* bp = (const float4*)b;
#pragma unroll
    for (int q = 0; q < 4; q++) {
        int c = lane + 32 * q;
        float4 gv = gp[c], bv = bp[c], o;
        o.x = (v[q].x - mean) * inv * gv.x + bv.x;
        o.y = (v[q].y - mean) * inv * gv.y + bv.y;
        o.z = (v[q].z - mean) * inv * gv.z + bv.z;
        o.w = (v[q].w - mean) * inv * gv.w + bv.w;
        if (do_relu) {
            o.x = fmaxf(o.x, 0.f); o.y = fmaxf(o.y, 0.f);
            o.z = fmaxf(o.z, 0.f); o.w = fmaxf(o.w, 0.f);
        }
        if (outf) ((float4*)(outf + (long long)warp * 512))[c] = o;
        if (outh) {
            __half2* hp = (__half2*)(outh + (long long)warp * 512);
            hp[c * 2 + 0] = __floats2half2_rn(o.x, o.y);
            hp[c * 2 + 1] = __floats2half2_rn(o.z, o.w);
        }
    }
}

// ---------------------------------------------------------------------------
// cos similarity + half GEMM inputs: hc = cos*prev, hs = (1-cos)*cur
// ---------------------------------------------------------------------------
__global__ __launch_bounds__(256) void cos_kernel(
    const float* __restrict__ spatial, float* __restrict__ cosv,
    __half* __restrict__ hc, __half* __restrict__ hs)
{
    int warp = (blockIdx.x * 256 + threadIdx.x) >> 5;
    int lane = threadIdx.x & 31;
    if (warp >= 50400) return;
    int i = warp % 50;
    int tq = (warp / 50) % 63;
    int b_ = warp / 3150;
    long long cur_off  = (((long long)b_ * 64 + tq + 1) * 50 + i) * 512;
    long long prev_off = (((long long)b_ * 64 + tq) * 50 + i) * 512;
    const float4* cp = (const float4*)(spatial + cur_off);
    const float4* pp = (const float4*)(spatial + prev_off);
    float4 cb[4], pb[4];
    float dt = 0.f, na = 0.f, nb = 0.f;
#pragma unroll
    for (int q = 0; q < 4; q++) {
        cb[q] = cp[lane + 32 * q];
        pb[q] = pp[lane + 32 * q];
        dt += cb[q].x * pb[q].x + cb[q].y * pb[q].y + cb[q].z * pb[q].z + cb[q].w * pb[q].w;
        na += cb[q].x * cb[q].x + cb[q].y * cb[q].y + cb[q].z * cb[q].z + cb[q].w * cb[q].w;
        nb += pb[q].x * pb[q].x + pb[q].y * pb[q].y + pb[q].z * pb[q].z + pb[q].w * pb[q].w;
    }
#pragma unroll
    for (int off = 16; off; off >>= 1) {
        dt += __shfl_xor_sync(0xffffffffu, dt, off);
        na += __shfl_xor_sync(0xffffffffu, na, off);
        nb += __shfl_xor_sync(0xffffffffu, nb, off);
    }
    float cv = dt / (fmaxf(sqrtf(na), 1e-8f) * fmaxf(sqrtf(nb), 1e-8f));
    if (lane == 0) cosv[warp] = cv;
    __half2* hcp = (__half2*)(hc + (long long)warp * 512);
    __half2* hsp = (__half2*)(hs + (long long)warp * 512);
    float w1 = 1.f - cv;
#pragma unroll
    for (int q = 0; q < 4; q++) {
        int c = lane + 32 * q;
        hcp[c * 2 + 0] = __floats2half2_rn(cv * pb[q].x, cv * pb[q].y);
        hcp[c * 2 + 1] = __floats2half2_rn(cv * pb[q].z, cv * pb[q].w);
        hsp[c * 2 + 0] = __floats2half2_rn(w1 * cb[q].x, w1 * cb[q].y);
        hsp[c * 2 + 1] = __floats2half2_rn(w1 * cb[q].z, w1 * cb[q].w);
    }
}

// ---------------------------------------------------------------------------
// copy t=0 rows of spatial into out_pre buffer
// ---------------------------------------------------------------------------
__global__ __launch_bounds__(256) void copy_t0_kernel(
    const float* __restrict__ src, float* __restrict__ dst)
{
    int idx = blockIdx.x * 256 + threadIdx.x;
    if (idx >= 800 * 128) return;
    int r = idx >> 7, hv = idx & 127;
    int b_ = r / 50, i = r % 50;
    long long row = ((long long)b_ * 64) * 50 + i;
    ((float4*)(dst + row * 512))[hv] = ((const float4*)(src + row * 512))[hv];
}

// ---------------------------------------------------------------------------
// Host launcher
// ---------------------------------------------------------------------------
extern "C" void kernel_launch(void* const* d_in, const int* in_sizes, int n_in,
                              void* d_out, int out_size)
{
    const float* visual = (const float*)d_in[0];
    const float* audio  = (const float*)d_in[1];
    const float* in_W   = (const float*)d_in[2];
    const float* in_b   = (const float*)d_in[3];
    const float* out_W  = (const float*)d_in[4];
    const float* out_b  = (const float*)d_in[5];

    float *node, *spatial, *t1, *t2, *attnb, *cosb;
    __half *hA, *hc, *hs, *ht3, *hnode, *wh;
    cudaGetSymbolAddress((void**)&node,    g_node);
    cudaGetSymbolAddress((void**)&spatial, g_spatial);
    cudaGetSymbolAddress((void**)&t1,      g_t1);
    cudaGetSymbolAddress((void**)&t2,      g_t2);
    cudaGetSymbolAddress((void**)&attnb,   g_attn);
    cudaGetSymbolAddress((void**)&cosb,    g_cos);
    cudaGetSymbolAddress((void**)&hA,      g_hA);
    cudaGetSymbolAddress((void**)&hc,      g_hc);
    cudaGetSymbolAddress((void**)&hs,      g_hs);
    cudaGetSymbolAddress((void**)&ht3,     g_ht3);
    cudaGetSymbolAddress((void**)&hnode,   g_hnode);
    cudaGetSymbolAddress((void**)&wh,      g_wh);

    const int smem_attn = ATTN_SMEM_FLOATS * 4;
    cudaFuncSetAttribute(attn_kernel,
                         cudaFuncAttributeMaxDynamicSharedMemorySize, smem_attn);
    cudaFuncSetAttribute(gemm_fp16,
                         cudaFuncAttributeMaxDynamicSharedMemorySize, GEMM_SMEM);

    const float* wsrc[8] = {
        in_W, (const float*)d_in[9], (const float*)d_in[11], (const float*)d_in[13],
        (const float*)d_in[17], (const float*)d_in[19], (const float*)d_in[21], out_W };
    for (int i = 0; i < 4; i++)
        wround2_kernel<<<512, 256>>>(wsrc[i * 2], wsrc[i * 2 + 1],
                                     wh + (long long)(i * 2) * 262144,
                                     wh + (long long)(i * 2 + 1) * 262144);

    concat_kernel<<<25600, 256>>>(visual, audio, hA);
    dim3 gAll(4, 200);                 // 256-row tiles: 200 * 256 = 51200
    dim3 gTmp(4, 197);                 // 197 * 256 = 50432 >= 50400
    gemm_fp16<<<gAll, 512, GEMM_SMEM>>>(hA, wh + 0 * 262144, in_b,
                                        nullptr, nullptr, node, nullptr,
                                        51200, 0);

    for (int L = 0; L < 2; L++) {
        int base = 6 + L * 8;
        const float* edge = (const float*)d_in[base + 0];
        const float* lng  = (const float*)d_in[base + 1];
        const float* lnb  = (const float*)d_in[base + 2];
        const float* bc   = (const float*)d_in[base + 4];
        const float* bs   = (const float*)d_in[base + 6];
        const __half* wc  = wh + (long long)(1 + L * 3) * 262144;
        const __half* ws  = wh + (long long)(2 + L * 3) * 262144;
        const __half* wo  = wh + (long long)(3 + L * 3) * 262144;

        attn_kernel<<<1024, 512, smem_attn>>>(node, edge, t2, attnb);
        ln_kernel<<<6400, 256>>>(t2, spatial, nullptr, lng, lnb, 51200, 1);
        cos_kernel<<<6300, 256>>>(spatial, cosb, hc, hs);
        gemm_fp16<<<gTmp, 512, GEMM_SMEM>>>(hc, wc, bc, nullptr, nullptr,
                                            t1, nullptr, 50400, 1);
        gemm_fp16<<<gTmp, 512, GEMM_SMEM>>>(hs, ws, bs, t1, spatial,
                                            t2, nullptr, 50400, 2);
        copy_t0_kernel<<<400, 256>>>(spatial, t2);
        ln_kernel<<<6400, 256>>>(t2, nullptr, ht3, lng, lnb, 51200, 0);
        gemm_fp16<<<gAll, 512, GEMM_SMEM>>>(ht3, wo, nullptr, node, nullptr,
                                            node, hnode, 51200, 3);
    }

    gemm_fp16<<<gAll, 512, GEMM_SMEM>>>(hnode, wh + 7LL * 262144, out_b,
                                        nullptr, nullptr, (float*)d_out,
                                        nullptr, 51200, 0);

    long long need = OUT_ELEMS + ATTN_ELEMS + COS_ELEMS;
    if ((long long)out_size >= need) {
        cudaMemcpyAsync((float*)d_out + OUT_ELEMS, attnb,
                        ATTN_ELEMS * sizeof(float), cudaMemcpyDeviceToDevice);
        cudaMemcpyAsync((float*)d_out + OUT_ELEMS + ATTN_ELEMS, cosb,
                        COS_ELEMS * sizeof(float), cudaMemcpyDeviceToDevice);
    }
}

// round 7
// speedup vs baseline: 1.2211x; 1.2211x over previous
#include <cuda_runtime.h>
#include <cuda_fp16.h>
#include <cstdint>

// ---------------------------------------------------------------------------
// Problem: B=16, T=64, N=49(+1)=50 nodes, D=H=512, WIN=7
// ---------------------------------------------------------------------------
#define NEGBIG (-1e9f)

static const long long OUT_ELEMS  = 51200LL * 512;
static const long long ATTN_ELEMS = 1024LL * 2500;
static const long long COS_ELEMS  = 50400LL;

// ---------------------------------------------------------------------------
// Device scratch
// ---------------------------------------------------------------------------
__device__ float  g_node[51200 * 512];
__device__ float  g_spatial[51200 * 512];
__device__ float  g_t1[51200 * 512];
__device__ float  g_t2[51200 * 512];
__device__ float  g_attn[1024 * 2500];
__device__ float  g_cos[50400];
__device__ __half g_hA[51200 * 512];
__device__ __half g_hc[50400 * 512];
__device__ __half g_hs[50400 * 512];
__device__ __half g_ht3[51200 * 512];
__device__ __half g_hnode[51200 * 512];
__device__ __half g_wh[8 * 512 * 512];

// ---------------------------------------------------------------------------
// helpers
// ---------------------------------------------------------------------------
__device__ __forceinline__ uint32_t smem_u32(const void* p) {
    uint32_t a;
    asm("{ .reg .u64 t; cvta.to.shared.u64 t, %1; cvt.u32.u64 %0, t; }"
        : "=r"(a) : "l"(p));
    return a;
}
__device__ __forceinline__ uint32_t sw128(uint32_t off) {
    return off ^ ((off >> 3) & 0x70);
}
__device__ __forceinline__ void cp16(uint32_t dst, const void* src) {
    asm volatile("cp.async.cg.shared.global [%0], [%1], 16;\n"
                 :: "r"(dst), "l"(src));
}
__device__ __forceinline__ void cp_commit() {
    asm volatile("cp.async.commit_group;\n" ::: "memory");
}
__device__ __forceinline__ void cp_wait1() {
    asm volatile("cp.async.wait_group 1;\n" ::: "memory");
}
__device__ __forceinline__ void ldm_x4(uint32_t r[4], uint32_t addr) {
    asm volatile("ldmatrix.sync.aligned.m8n8.x4.shared.b16 {%0,%1,%2,%3}, [%4];"
                 : "=r"(r[0]), "=r"(r[1]), "=r"(r[2]), "=r"(r[3]) : "r"(addr));
}
__device__ __forceinline__ void mma_fp16(
    float c[4], uint32_t a0, uint32_t a1, uint32_t a2, uint32_t a3,
    uint32_t b0, uint32_t b1)
{
    asm volatile(
        "mma.sync.aligned.m16n8k16.row.col.f32.f16.f16.f32 "
        "{%0,%1,%2,%3}, {%4,%5,%6,%7}, {%8,%9}, {%0,%1,%2,%3};\n"
        : "+f"(c[0]), "+f"(c[1]), "+f"(c[2]), "+f"(c[3])
        : "r"(a0), "r"(a1), "r"(a2), "r"(a3), "r"(b0), "r"(b1));
}
__device__ __forceinline__ float wreduce(float s) {
#pragma unroll
    for (int o = 16; o; o >>= 1) s += __shfl_xor_sync(0xffffffffu, s, o);
    return s;
}

// ---------------------------------------------------------------------------
// weights -> half, two per launch
// ---------------------------------------------------------------------------
__global__ __launch_bounds__(256) void wround2_kernel(
    const float* __restrict__ s0, const float* __restrict__ s1,
    __half* __restrict__ d0, __half* __restrict__ d1)
{
    const float* s = (blockIdx.x < 256) ? s0 : s1;
    __half2* d = (__half2*)((blockIdx.x < 256) ? d0 : d1);
    int i = (blockIdx.x & 255) * 256 + threadIdx.x;
    float4 v = ((const float4*)s)[i];
    d[i * 2 + 0] = __floats2half2_rn(v.x, v.y);
    d[i * 2 + 1] = __floats2half2_rn(v.z, v.w);
}

// ---------------------------------------------------------------------------
// concat(visual, audio) -> half [51200, 512]
// ---------------------------------------------------------------------------
__global__ __launch_bounds__(256) void concat_kernel(
    const float* __restrict__ vis, const float* __restrict__ aud,
    __half* __restrict__ out)
{
    long long idx = (long long)blockIdx.x * 256 + threadIdx.x;
    if (idx >= (long long)51200 * 128) return;
    long long r = idx >> 7;
    int hv = (int)(idx & 127);
    int bt = (int)(r / 50), i = (int)(r % 50);
    float4 v;
    if (i < 49)
        v = ((const float4*)vis)[((long long)bt * 49 + i) * 128 + hv];
    else
        v = ((const float4*)aud)[(long long)bt * 128 + hv];
    __half2* d = (__half2*)out;
    d[idx * 2 + 0] = __floats2half2_rn(v.x, v.y);
    d[idx * 2 + 1] = __floats2half2_rn(v.z, v.w);
}

// ---------------------------------------------------------------------------
// fp16 tensor-core NT GEMM (round-4 config): CTA 128x128, k-tile 64,
// 3-stage cp.async pipeline, 256 threads / 8 warps, 2 CTAs/SM.
// ---------------------------------------------------------------------------
#define STAGE_BYTES 32768
#define GEMM_SMEM   (3 * STAGE_BYTES)

__global__ __launch_bounds__(256) void gemm_fp16(
    const __half* __restrict__ A, const __half* __restrict__ W,
    const float* __restrict__ bias, const float* __restrict__ add1,
    const float* __restrict__ add2, float* __restrict__ C,
    __half* __restrict__ Ch, int M, int mode)
{
    extern __shared__ char smem[];
    const uint32_t sb = smem_u32(smem);

    const int tid = threadIdx.x;
    const int wid = tid >> 5, lane = tid & 31;
    const int wm = wid >> 2, wn = wid & 3;
    const int g = lane >> 2, t = lane & 3;
    const int m0 = blockIdx.y * 128;
    const int n0 = blockIdx.x * 128;

    float acc[4][4][4];
#pragma unroll
    for (int mf = 0; mf < 4; mf++)
#pragma unroll
        for (int nf = 0; nf < 4; nf++)
#pragma unroll
            for (int q = 0; q < 4; q++) acc[mf][nf][q] = 0.f;

    auto load_stage = [&](int s) {
        const int buf = s % 3;
        const uint32_t ab = sb + buf * STAGE_BYTES;
        const uint32_t bb = ab + 16384;
        const int k0 = s * 64;
#pragma unroll
        for (int i = 0; i < 8; i++) {
            int o = tid + i * 256;
            int oo = o & 1023;
            int row = oo >> 3, c = oo & 7;
            uint32_t off = sw128((uint32_t)(row * 128 + c * 16));
            if (o < 1024) {
                int sr = m0 + row; if (sr > M - 1) sr = M - 1;
                cp16(ab + off, A + (long long)sr * 512 + k0 + c * 8);
            } else {
                cp16(bb + off, W + (long long)(n0 + row) * 512 + k0 + c * 8);
            }
        }
    };

    load_stage(0); cp_commit();
    load_stage(1); cp_commit();

    const int a_row = (lane & 15);
    const int a_c16 = (lane >> 4);
    const int b_row = ((lane >> 4) << 3) + (lane & 7);
    const int b_c16 = ((lane >> 3) & 1);

    for (int s = 0; s < 8; s++) {
        cp_wait1();
        __syncthreads();
        const int buf = s % 3;
        const uint32_t ab = sb + buf * STAGE_BYTES;
        const uint32_t bb = ab + 16384;

#pragma unroll
        for (int ks = 0; ks < 4; ks++) {
            uint32_t af[4][4], bf[2][4];
#pragma unroll
            for (int mf = 0; mf < 4; mf++) {
                int m = wm * 64 + mf * 16 + a_row;
                ldm_x4(af[mf], ab + sw128((uint32_t)(m * 128 + ks * 32 + a_c16 * 16)));
            }
#pragma unroll
            for (int np = 0; np < 2; np++) {
                int n = wn * 32 + np * 16 + b_row;
                ldm_x4(bf[np], bb + sw128((uint32_t)(n * 128 + ks * 32 + b_c16 * 16)));
            }
#pragma unroll
            for (int mf = 0; mf < 4; mf++) {
                mma_fp16(acc[mf][0], af[mf][0], af[mf][1], af[mf][2], af[mf][3],
                         bf[0][0], bf[0][1]);
                mma_fp16(acc[mf][1], af[mf][0], af[mf][1], af[mf][2], af[mf][3],
                         bf[0][2], bf[0][3]);
                mma_fp16(acc[mf][2], af[mf][0], af[mf][1], af[mf][2], af[mf][3],
                         bf[1][0], bf[1][1]);
                mma_fp16(acc[mf][3], af[mf][0], af[mf][1], af[mf][2], af[mf][3],
                         bf[1][2], bf[1][3]);
            }
        }
        if (s + 2 < 8) load_stage(s + 2);
        cp_commit();
    }

#pragma unroll
    for (int mf = 0; mf < 4; mf++) {
#pragma unroll
        for (int h = 0; h < 2; h++) {
            int m = m0 + wm * 64 + mf * 16 + g + h * 8;
            if (m >= M) continue;
            long long orow;
            if (mode == 2) {
                int b_ = m / 3150, tq = (m / 50) % 63, i_ = m % 50;
                orow = ((long long)(b_ * 64 + tq + 1) * 50 + i_) * 512;
            } else {
                orow = (long long)m * 512;
            }
            long long arow = (long long)m * 512;
#pragma unroll
            for (int nf = 0; nf < 4; nf++) {
                int n = n0 + wn * 32 + nf * 8 + t * 2;
                float v0 = acc[mf][nf][h * 2 + 0];
                float v1 = acc[mf][nf][h * 2 + 1];
                float o0, o1;
                if (mode == 0) {
                    o0 = v0 + bias[n]; o1 = v1 + bias[n + 1];
                } else if (mode == 1) {
                    o0 = fmaxf(v0 + bias[n], 0.f);
                    o1 = fmaxf(v1 + bias[n + 1], 0.f);
                } else if (mode == 2) {
                    o0 = add2[orow + n]     + add1[arow + n]     + fmaxf(v0 + bias[n], 0.f);
                    o1 = add2[orow + n + 1] + add1[arow + n + 1] + fmaxf(v1 + bias[n + 1], 0.f);
                } else {
                    o0 = add1[arow + n]     + fmaxf(v0, 0.f);
                    o1 = add1[arow + n + 1] + fmaxf(v1, 0.f);
                }
                *(float2*)(C + orow + n) = make_float2(o0, o1);
                if (mode == 3)
                    *(__half2*)(Ch + orow + n) = __floats2half2_rn(o0, o1);
            }
        }
    }
}

// ---------------------------------------------------------------------------
// Sparse fused attention for one (b,t), 512 threads:
// window-sparse Gram + mask + softmax + sparse aggregation + fused LN+relu.
// Writes spatial = relu(LN(agg + x)) and the dense attention matrix.
// ---------------------------------------------------------------------------
#define ATTN_SMEM_FLOATS (50*512 + 3*512 + 50*52 + 6*52 + 8)

__global__ __launch_bounds__(512) void attn_kernel(
    const float* __restrict__ x, const float* __restrict__ edge,
    const float* __restrict__ lng, const float* __restrict__ lnb,
    float* __restrict__ spatial, float* __restrict__ attn_out)
{
    extern __shared__ float sm[];
    float* xs  = sm;               // [50][512]
    float* es  = xs + 50 * 512;    // [3][512]
    float* S   = es + 3 * 512;     // [50][52] scores / attn
    float* rq  = S + 50 * 52;
    float* rk0 = rq + 52;
    float* rk1 = rk0 + 52;
    float* d0  = rk1 + 52;
    float* d1  = d0 + 52;
    float* d2  = d1 + 52;
    float* sc  = d2 + 52;          // E0,E1,E2, rk2

    const int bt = blockIdx.x;
    const int tid = threadIdx.x;
    const int wid = tid >> 5, lane = tid & 31;
    const float* xg = x + (long long)bt * 50 * 512;

    for (int idx = tid; idx < 50 * 128; idx += 512)
        ((float4*)xs)[idx] = ((const float4*)xg)[idx];
    for (int idx = tid; idx < 3 * 128; idx += 512)
        ((float4*)es)[idx] = ((const float4*)edge)[idx];
    __syncthreads();

    // ---------------- sparse warp-dots ----------------
    // lane owns floats [lane*16, lane*16+16) of each 512-row
    auto slice_dot = [&](const float4 a[4], const float* rb) -> float {
        const float4* b4 = (const float4*)rb + lane * 4;
        float s = 0.f;
#pragma unroll
        for (int q = 0; q < 4; q++) {
            float4 b = b4[q];
            s += a[q].x * b.x + a[q].y * b.y + a[q].z * b.z + a[q].w * b.w;
        }
        return wreduce(s);
    };

    // window dots for i < 49 (warp per row)
    for (int i = wid; i < 49; i += 16) {
        float4 ai[4];
        const float4* xi4 = (const float4*)(xs + i * 512) + lane * 4;
#pragma unroll
        for (int q = 0; q < 4; q++) ai[q] = xi4[q];
        int qr = i / 7, qc = i - qr * 7;
        int r0 = qr - 1; if (r0 < 0) r0 = 0;
        int c0 = qc - 1; if (c0 < 0) c0 = 0; if (c0 > 4) c0 = 4;
        for (int a = 0; a < 3; a++) {
            int kr = r0 + a;
            if (kr > 6) break;
            for (int b = 0; b < 3; b++) {
                int j = kr * 7 + c0 + b;
                float v = slice_dot(ai, xs + j * 512);
                if (lane == 0) S[i * 52 + j] = v;
            }
        }
    }
    // row/col 49
    {
        float4 a49[4];
        const float4* x49 = (const float4*)(xs + 49 * 512) + lane * 4;
#pragma unroll
        for (int q = 0; q < 4; q++) a49[q] = x49[q];
        for (int j = wid; j < 50; j += 16) {
            float v = slice_dot(a49, xs + j * 512);
            if (lane == 0) { S[49 * 52 + j] = v; S[j * 52 + 49] = v; }
        }
    }
    // edge dots d_k[i] and E_k
    for (int p = wid; p < 153; p += 16) {
        if (p < 150) {
            int i = p / 3, k = p - i * 3;
            float4 ai[4];
            const float4* xi4 = (const float4*)(xs + i * 512) + lane * 4;
#pragma unroll
            for (int q = 0; q < 4; q++) ai[q] = xi4[q];
            float v = slice_dot(ai, es + k * 512);
            if (lane == 0) (k == 0 ? d0 : k == 1 ? d1 : d2)[i] = v;
        } else {
            int k = p - 150;
            float4 ek[4];
            const float4* e4 = (const float4*)(es + k * 512) + lane * 4;
#pragma unroll
            for (int q = 0; q < 4; q++) ek[q] = e4[q];
            float v = slice_dot(ek, es + k * 512);
            if (lane == 0) sc[k] = v;
        }
    }
    __syncthreads();

    // ---------------- norms ----------------
    if (tid < 50) {
        float gd = S[tid * 53];
        rq[tid]  = 1.f / fmaxf(sqrtf(gd), 1e-12f);
        rk0[tid] = 1.f / fmaxf(sqrtf(gd + 2.f * d0[tid] + sc[0]), 1e-12f);
        rk1[tid] = 1.f / fmaxf(sqrtf(gd + 2.f * d1[tid] + sc[1]), 1e-12f);
    } else if (tid == 50) {
        sc[3] = 1.f / fmaxf(sqrtf(S[49 * 53] + 2.f * d2[49] + sc[2]), 1e-12f);
    }
    __syncthreads();

    const float rk2  = sc[3];
    const float d149 = d1[49];
    const float rq49 = rq[49];

    // ---------------- scores (dense, in place) ----------------
    for (int p = tid; p < 2500; p += 512) {
        int i = p / 50, j = p - i * 50;
        float v;
        if (i == j)        v = NEGBIG;
        else if (j == 49)  v = (S[i * 52 + 49] + d2[i]) * rq[i] * rk2;
        else if (i == 49)  v = (S[49 * 52 + j] + d149) * rq49 * rk1[j];
        else {
            int qr = i / 7, qc = i - qr * 7;
            int kr = j / 7, kc = j - kr * 7;
            int r0 = qr - 1; if (r0 < 0) r0 = 0;
            int c0 = qc - 1; if (c0 < 0) c0 = 0; if (c0 > 4) c0 = 4;
            bool ok = (kr >= r0) && (kr <= r0 + 2) && (kc >= c0) && (kc <= c0 + 2);
            v = ok ? (S[i * 52 + j] + d0[i]) * rq[i] * rk0[j] : NEGBIG;
        }
        S[i * 52 + j] = v;
    }
    __syncthreads();

    // ---------------- softmax ----------------
    if (tid < 50) {
        float* row = S + tid * 52;
        float mx = -3.4e38f;
        for (int j = 0; j < 50; j++) mx = fmaxf(mx, row[j]);
        float s = 0.f;
        for (int j = 0; j < 50; j++) { float e = expf(row[j] - mx); row[j] = e; s += e; }
        float inv = 1.f / s;
        for (int j = 0; j < 50; j++) row[j] *= inv;
    }
    __syncthreads();

    // ---------------- write attention ----------------
    for (int p = tid; p < 2500; p += 512)
        attn_out[(long long)bt * 2500 + p] = S[(p / 50) * 52 + (p % 50)];

    // ---------------- sparse aggregation + residual + LN + relu -----------
    for (int i = wid; i < 50; i += 16) {
        float4 acc[4];
#pragma unroll
        for (int q = 0; q < 4; q++) acc[q] = make_float4(0.f, 0.f, 0.f, 0.f);
        const float aL = S[i * 52 + 49];

        auto addj = [&](int j, float w) {
            const float4* xj = (const float4*)(xs + j * 512) + lane * 4;
#pragma unroll
            for (int q = 0; q < 4; q++) {
                float4 v = xj[q];
                acc[q].x += w * v.x; acc[q].y += w * v.y;
                acc[q].z += w * v.z; acc[q].w += w * v.w;
            }
        };

        if (i < 49) {
            int qr = i / 7, qc = i - qr * 7;
            int r0 = qr - 1; if (r0 < 0) r0 = 0;
            int c0 = qc - 1; if (c0 < 0) c0 = 0; if (c0 > 4) c0 = 4;
            for (int a = 0; a < 3; a++) {
                int kr = r0 + a;
                if (kr > 6) break;
                for (int b = 0; b < 3; b++) {
                    int j = kr * 7 + c0 + b;
                    addj(j, S[i * 52 + j]);
                }
            }
            addj(49, aL);
        } else {
            for (int j = 0; j < 49; j++) addj(j, S[49 * 52 + j]);
        }

        // y = acc + (1-aL)*esel + aL*e2 + x_i
        const float4* ese = (const float4*)(es + (i < 49 ? 0 : 512)) + lane * 4;
        const float4* e2v = (const float4*)(es + 1024) + lane * 4;
        const float4* xi4 = (const float4*)(xs + i * 512) + lane * 4;
        const float w1 = 1.f - aL;
        float4 y[4];
        float s1 = 0.f;
#pragma unroll
        for (int q = 0; q < 4; q++) {
            float4 e0q = ese[q], e2q = e2v[q], xq = xi4[q];
            y[q].x = acc[q].x + w1 * e0q.x + aL * e2q.x + xq.x;
            y[q].y = acc[q].y + w1 * e0q.y + aL * e2q.y + xq.y;
            y[q].z = acc[q].z + w1 * e0q.z + aL * e2q.z + xq.z;
            y[q].w = acc[q].w + w1 * e0q.w + aL * e2q.w + xq.w;
            s1 += y[q].x + y[q].y + y[q].z + y[q].w;
        }
        s1 = wreduce(s1);
        float mean = s1 * (1.f / 512.f);
        float s2 = 0.f;
#pragma unroll
        for (int q = 0; q < 4; q++) {
            float dx = y[q].x - mean, dy = y[q].y - mean;
            float dz = y[q].z - mean, dw = y[q].w - mean;
            s2 += dx * dx + dy * dy + dz * dz + dw * dw;
        }
        s2 = wreduce(s2);
        float inv = rsqrtf(s2 * (1.f / 512.f) + 1e-5f);

        const float4* gp = (const float4*)lng + lane * 4;
        const float4* bp = (const float4*)lnb + lane * 4;
        float4* op = (float4*)(spatial + ((long long)bt * 50 + i) * 512) + lane * 4;
#pragma unroll
        for (int q = 0; q < 4; q++) {
            float4 gv = gp[q], bv = bp[q], o;
            o.x = fmaxf((y[q].x - mean) * inv * gv.x + bv.x, 0.f);
            o.y = fmaxf((y[q].y - mean) * inv * gv.y + bv.y, 0.f);
            o.z = fmaxf((y[q].z - mean) * inv * gv.z + bv.z, 0.f);
            o.w = fmaxf((y[q].w - mean) * inv * gv.w + bv.w, 0.f);
            op[q] = o;
        }
    }
}

// ---------------------------------------------------------------------------
// LayerNorm (warp per 512-row); optional relu; optional t=0 source override.
// Writes fp32 (if outf) and/or half (if outh).
// ---------------------------------------------------------------------------
__global__ __launch_bounds__(256) void ln_kernel(
    const float* __restrict__ in, const float* __restrict__ in0,
    float* __restrict__ outf, __half* __restrict__ outh,
    const float* __restrict__ g, const float* __restrict__ b,
    int rows, int do_relu)
{
    int warp = (blockIdx.x * 256 + threadIdx.x) >> 5;
    int lane = threadIdx.x & 31;
    if (warp >= rows) return;
    const float* src = in;
    if (in0) {
        int t = (warp / 50) & 63;
        if (t == 0) src = in0;
    }
    const float4* ip = (const float4*)(src + (long long)warp * 512);
    float4 v[4];
    float s = 0.f;
#pragma unroll
    for (int q = 0; q < 4; q++) {
        v[q] = ip[lane + 32 * q];
        s += v[q].x + v[q].y + v[q].z + v[q].w;
    }
#pragma unroll
    for (int off = 16; off; off >>= 1) s += __shfl_xor_sync(0xffffffffu, s, off);
    float mean = s * (1.f / 512.f);
    float ss = 0.f;
#pragma unroll
    for (int q = 0; q < 4; q++) {
        float dx = v[q].x - mean, dy = v[q].y - mean, dz = v[q].z - mean, dw = v[q].w - mean;
        ss += dx * dx + dy * dy + dz * dz + dw * dw;
    }
#pragma unroll
    for (int off = 16; off; off >>= 1) ss += __shfl_xor_sync(0xffffffffu, ss, off);
    float inv = rsqrtf(ss * (1.f / 512.f) + 1e-5f);
    const float4* gp = (const float4*)g;
    const float4* bp = (const float4*)b;
#pragma unroll
    for (int q = 0; q < 4; q++) {
        int c = lane + 32 * q;
        float4 gv = gp[c], bv = bp[c], o;
        o.x = (v[q].x - mean) * inv * gv.x + bv.x;
        o.y = (v[q].y - mean) * inv * gv.y + bv.y;
        o.z = (v[q].z - mean) * inv * gv.z + bv.z;
        o.w = (v[q].w - mean) * inv * gv.w + bv.w;
        if (do_relu) {
            o.x = fmaxf(o.x, 0.f); o.y = fmaxf(o.y, 0.f);
            o.z = fmaxf(o.z, 0.f); o.w = fmaxf(o.w, 0.f);
        }
        if (outf) ((float4*)(outf + (long long)warp * 512))[c] = o;
        if (outh) {
            __half2* hp = (__half2*)(outh + (long long)warp * 512);
            hp[c * 2 + 0] = __floats2half2_rn(o.x, o.y);
            hp[c * 2 + 1] = __floats2half2_rn(o.z, o.w);
        }
    }
}

// ---------------------------------------------------------------------------
// cos similarity + half GEMM inputs: hc = cos*prev, hs = (1-cos)*cur
// ---------------------------------------------------------------------------
__global__ __launch_bounds__(256) void cos_kernel(
    const float* __restrict__ spatial, float* __restrict__ cosv,
    __half* __restrict__ hc, __half* __restrict__ hs)
{
    int warp = (blockIdx.x * 256 + threadIdx.x) >> 5;
    int lane = threadIdx.x & 31;
    if (warp >= 50400) return;
    int i = warp % 50;
    int tq = (warp / 50) % 63;
    int b_ = warp / 3150;
    long long cur_off  = (((long long)b_ * 64 + tq + 1) * 50 + i) * 512;
    long long prev_off = (((long long)b_ * 64 + tq) * 50 + i) * 512;
    const float4* cp = (const float4*)(spatial + cur_off);
    const float4* pp = (const float4*)(spatial + prev_off);
    float4 cb[4], pb[4];
    float dt = 0.f, na = 0.f, nb = 0.f;
#pragma unroll
    for (int q = 0; q < 4; q++) {
        cb[q] = cp[lane + 32 * q];
        pb[q] = pp[lane + 32 * q];
        dt += cb[q].x * pb[q].x + cb[q].y * pb[q].y + cb[q].z * pb[q].z + cb[q].w * pb[q].w;
        na += cb[q].x * cb[q].x + cb[q].y * cb[q].y + cb[q].z * cb[q].z + cb[q].w * cb[q].w;
        nb += pb[q].x * pb[q].x + pb[q].y * pb[q].y + pb[q].z * pb[q].z + pb[q].w * pb[q].w;
    }
#pragma unroll
    for (int off = 16; off; off >>= 1) {
        dt += __shfl_xor_sync(0xffffffffu, dt, off);
        na += __shfl_xor_sync(0xffffffffu, na, off);
        nb += __shfl_xor_sync(0xffffffffu, nb, off);
    }
    float cv = dt / (fmaxf(sqrtf(na), 1e-8f) * fmaxf(sqrtf(nb), 1e-8f));
    if (lane == 0) cosv[warp] = cv;
    __half2* hcp = (__half2*)(hc + (long long)warp * 512);
    __half2* hsp = (__half2*)(hs + (long long)warp * 512);
    float w1 = 1.f - cv;
#pragma unroll
    for (int q = 0; q < 4; q++) {
        int c = lane + 32 * q;
        hcp[c * 2 + 0] = __floats2half2_rn(cv * pb[q].x, cv * pb[q].y);
        hcp[c * 2 + 1] = __floats2half2_rn(cv * pb[q].z, cv * pb[q].w);
        hsp[c * 2 + 0] = __floats2half2_rn(w1 * cb[q].x, w1 * cb[q].y);
        hsp[c * 2 + 1] = __floats2half2_rn(w1 * cb[q].z, w1 * cb[q].w);
    }
}

// ---------------------------------------------------------------------------
// Host launcher
// ---------------------------------------------------------------------------
extern "C" void kernel_launch(void* const* d_in, const int* in_sizes, int n_in,
                              void* d_out, int out_size)
{
    const float* visual = (const float*)d_in[0];
    const float* audio  = (const float*)d_in[1];
    const float* in_W   = (const float*)d_in[2];
    const float* in_b   = (const float*)d_in[3];
    const float* out_W  = (const float*)d_in[4];
    const float* out_b  = (const float*)d_in[5];

    float *node, *spatial, *t1, *t2, *attnb, *cosb;
    __half *hA, *hc, *hs, *ht3, *hnode, *wh;
    cudaGetSymbolAddress((void**)&node,    g_node);
    cudaGetSymbolAddress((void**)&spatial, g_spatial);
    cudaGetSymbolAddress((void**)&t1,      g_t1);
    cudaGetSymbolAddress((void**)&t2,      g_t2);
    cudaGetSymbolAddress((void**)&attnb,   g_attn);
    cudaGetSymbolAddress((void**)&cosb,    g_cos);
    cudaGetSymbolAddress((void**)&hA,      g_hA);
    cudaGetSymbolAddress((void**)&hc,      g_hc);
    cudaGetSymbolAddress((void**)&hs,      g_hs);
    cudaGetSymbolAddress((void**)&ht3,     g_ht3);
    cudaGetSymbolAddress((void**)&hnode,   g_hnode);
    cudaGetSymbolAddress((void**)&wh,      g_wh);

    const int smem_attn = ATTN_SMEM_FLOATS * 4;
    cudaFuncSetAttribute(attn_kernel,
                         cudaFuncAttributeMaxDynamicSharedMemorySize, smem_attn);
    cudaFuncSetAttribute(gemm_fp16,
                         cudaFuncAttributeMaxDynamicSharedMemorySize, GEMM_SMEM);

    const float* wsrc[8] = {
        in_W, (const float*)d_in[9], (const float*)d_in[11], (const float*)d_in[13],
        (const float*)d_in[17], (const float*)d_in[19], (const float*)d_in[21], out_W };
    for (int i = 0; i < 4; i++)
        wround2_kernel<<<512, 256>>>(wsrc[i * 2], wsrc[i * 2 + 1],
                                     wh + (long long)(i * 2) * 262144,
                                     wh + (long long)(i * 2 + 1) * 262144);

    concat_kernel<<<25600, 256>>>(visual, audio, hA);    // launch #5
    dim3 gAll(4, 400);
    dim3 gTmp(4, 394);
    gemm_fp16<<<gAll, 256, GEMM_SMEM>>>(hA, wh + 0 * 262144, in_b,   // launch #6
                                        nullptr, nullptr, node, nullptr,
                                        51200, 0);

    for (int L = 0; L < 2; L++) {
        int base = 6 + L * 8;
        const float* edge = (const float*)d_in[base + 0];
        const float* lng  = (const float*)d_in[base + 1];
        const float* lnb  = (const float*)d_in[base + 2];
        const float* bc   = (const float*)d_in[base + 4];
        const float* bs   = (const float*)d_in[base + 6];
        const __half* wc  = wh + (long long)(1 + L * 3) * 262144;
        const __half* ws  = wh + (long long)(2 + L * 3) * 262144;
        const __half* wo  = wh + (long long)(3 + L * 3) * 262144;

        // attn + fused LN+relu -> spatial
        attn_kernel<<<1024, 512, smem_attn>>>(node, edge, lng, lnb,
                                              spatial, attnb);
        cos_kernel<<<6300, 256>>>(spatial, cosb, hc, hs);
        gemm_fp16<<<gTmp, 256, GEMM_SMEM>>>(hc, wc, bc, nullptr, nullptr,
                                            t1, nullptr, 50400, 1);
        gemm_fp16<<<gTmp, 256, GEMM_SMEM>>>(hs, ws, bs, t1, spatial,
                                            t2, nullptr, 50400, 2);
        // LN (t=0 rows sourced from spatial) -> half ht3
        ln_kernel<<<6400, 256>>>(t2, spatial, nullptr, ht3, lng, lnb, 51200, 0);
        gemm_fp16<<<gAll, 256, GEMM_SMEM>>>(ht3, wo, nullptr, node, nullptr,
                                            node, hnode, 51200, 3);
    }

    gemm_fp16<<<gAll, 256, GEMM_SMEM>>>(hnode, wh + 7LL * 262144, out_b,
                                        nullptr, nullptr, (float*)d_out,
                                        nullptr, 51200, 0);

    long long need = OUT_ELEMS + ATTN_ELEMS + COS_ELEMS;
    if ((long long)out_size >= need) {
        cudaMemcpyAsync((float*)d_out + OUT_ELEMS, attnb,
                        ATTN_ELEMS * sizeof(float), cudaMemcpyDeviceToDevice);
        cudaMemcpyAsync((float*)d_out + OUT_ELEMS + ATTN_ELEMS, cosb,
                        COS_ELEMS * sizeof(float), cudaMemcpyDeviceToDevice);
    }
}

// round 8
// speedup vs baseline: 1.3052x; 1.0689x over previous
#include <cuda_runtime.h>
#include <cuda_fp16.h>
#include <cstdint>

// ---------------------------------------------------------------------------
// Problem: B=16, T=64, N=49(+1)=50 nodes, D=H=512, WIN=7
// ---------------------------------------------------------------------------
#define NEGBIG (-1e9f)

static const long long OUT_ELEMS  = 51200LL * 512;
static const long long ATTN_ELEMS = 1024LL * 2500;
static const long long COS_ELEMS  = 50400LL;

// ---------------------------------------------------------------------------
// Device scratch
// ---------------------------------------------------------------------------
__device__ float  g_node[51200 * 512];
__device__ float  g_spatial[51200 * 512];
__device__ float  g_t1[51200 * 512];
__device__ float  g_t2[51200 * 512];
__device__ float  g_attn[1024 * 2500];
__device__ float  g_cos[50400];
__device__ __half g_hA[51200 * 512];
__device__ __half g_hc[50400 * 512];
__device__ __half g_hs[50400 * 512];
__device__ __half g_ht3[51200 * 512];
__device__ __half g_hnode[51200 * 512];
__device__ __half g_wh[8 * 512 * 512];

// ---------------------------------------------------------------------------
// helpers
// ---------------------------------------------------------------------------
__device__ __forceinline__ uint32_t smem_u32(const void* p) {
    uint32_t a;
    asm("{ .reg .u64 t; cvta.to.shared.u64 t, %1; cvt.u32.u64 %0, t; }"
        : "=r"(a) : "l"(p));
    return a;
}
__device__ __forceinline__ uint32_t sw128(uint32_t off) {
    return off ^ ((off >> 3) & 0x70);
}
__device__ __forceinline__ void cp16(uint32_t dst, const void* src) {
    asm volatile("cp.async.cg.shared.global [%0], [%1], 16;\n"
                 :: "r"(dst), "l"(src));
}
__device__ __forceinline__ void cp_commit() {
    asm volatile("cp.async.commit_group;\n" ::: "memory");
}
__device__ __forceinline__ void cp_wait1() {
    asm volatile("cp.async.wait_group 1;\n" ::: "memory");
}
__device__ __forceinline__ void ldm_x4(uint32_t r[4], uint32_t addr) {
    asm volatile("ldmatrix.sync.aligned.m8n8.x4.shared.b16 {%0,%1,%2,%3}, [%4];"
                 : "=r"(r[0]), "=r"(r[1]), "=r"(r[2]), "=r"(r[3]) : "r"(addr));
}
__device__ __forceinline__ void mma_fp16(
    float c[4], uint32_t a0, uint32_t a1, uint32_t a2, uint32_t a3,
    uint32_t b0, uint32_t b1)
{
    asm volatile(
        "mma.sync.aligned.m16n8k16.row.col.f32.f16.f16.f32 "
        "{%0,%1,%2,%3}, {%4,%5,%6,%7}, {%8,%9}, {%0,%1,%2,%3};\n"
        : "+f"(c[0]), "+f"(c[1]), "+f"(c[2]), "+f"(c[3])
        : "r"(a0), "r"(a1), "r"(a2), "r"(a3), "r"(b0), "r"(b1));
}
__device__ __forceinline__ float wreduce(float s) {
#pragma unroll
    for (int o = 16; o; o >>= 1) s += __shfl_xor_sync(0xffffffffu, s, o);
    return s;
}
// per-lane 16-float partial dot (no reduce)
__device__ __forceinline__ float dot16(const float4 a[4], const float* rb, int lane) {
    const float4* b4 = (const float4*)rb + lane * 4;
    float s = 0.f;
#pragma unroll
    for (int q = 0; q < 4; q++) {
        float4 b = b4[q];
        s += a[q].x * b.x + a[q].y * b.y + a[q].z * b.z + a[q].w * b.w;
    }
    return s;
}

// ---------------------------------------------------------------------------
// all 8 weights -> half in one launch (grid 2048)
// ---------------------------------------------------------------------------
__global__ __launch_bounds__(256) void wround8_kernel(
    const float* s0, const float* s1, const float* s2, const float* s3,
    const float* s4, const float* s5, const float* s6, const float* s7,
    __half* __restrict__ dst)
{
    int w = blockIdx.x >> 8;
    const float* s =
        (w == 0) ? s0 : (w == 1) ? s1 : (w == 2) ? s2 : (w == 3) ? s3 :
        (w == 4) ? s4 : (w == 5) ? s5 : (w == 6) ? s6 : s7;
    __half2* d = (__half2*)(dst + (long long)w * 262144);
    int i = (blockIdx.x & 255) * 256 + threadIdx.x;
    float4 v = ((const float4*)s)[i];
    d[i * 2 + 0] = __floats2half2_rn(v.x, v.y);
    d[i * 2 + 1] = __floats2half2_rn(v.z, v.w);
}

// ---------------------------------------------------------------------------
// concat(visual, audio) -> half [51200, 512]
// ---------------------------------------------------------------------------
__global__ __launch_bounds__(256) void concat_kernel(
    const float* __restrict__ vis, const float* __restrict__ aud,
    __half* __restrict__ out)
{
    long long idx = (long long)blockIdx.x * 256 + threadIdx.x;
    if (idx >= (long long)51200 * 128) return;
    long long r = idx >> 7;
    int hv = (int)(idx & 127);
    int bt = (int)(r / 50), i = (int)(r % 50);
    float4 v;
    if (i < 49)
        v = ((const float4*)vis)[((long long)bt * 49 + i) * 128 + hv];
    else
        v = ((const float4*)aud)[(long long)bt * 128 + hv];
    __half2* d = (__half2*)out;
    d[idx * 2 + 0] = __floats2half2_rn(v.x, v.y);
    d[idx * 2 + 1] = __floats2half2_rn(v.z, v.w);
}

// ---------------------------------------------------------------------------
// fp16 tensor-core NT GEMM: CTA 128x128, k-tile 64, 3-stage cp.async,
// 256 threads / 8 warps, 2 CTAs/SM.
// ---------------------------------------------------------------------------
#define STAGE_BYTES 32768
#define GEMM_SMEM   (3 * STAGE_BYTES)

__global__ __launch_bounds__(256) void gemm_fp16(
    const __half* __restrict__ A, const __half* __restrict__ W,
    const float* __restrict__ bias, const float* __restrict__ add1,
    const float* __restrict__ add2, float* __restrict__ C,
    __half* __restrict__ Ch, int M, int mode)
{
    extern __shared__ char smem[];
    const uint32_t sb = smem_u32(smem);

    const int tid = threadIdx.x;
    const int wid = tid >> 5, lane = tid & 31;
    const int wm = wid >> 2, wn = wid & 3;
    const int g = lane >> 2, t = lane & 3;
    const int m0 = blockIdx.y * 128;
    const int n0 = blockIdx.x * 128;

    float acc[4][4][4];
#pragma unroll
    for (int mf = 0; mf < 4; mf++)
#pragma unroll
        for (int nf = 0; nf < 4; nf++)
#pragma unroll
            for (int q = 0; q < 4; q++) acc[mf][nf][q] = 0.f;

    auto load_stage = [&](int s) {
        const int buf = s % 3;
        const uint32_t ab = sb + buf * STAGE_BYTES;
        const uint32_t bb = ab + 16384;
        const int k0 = s * 64;
#pragma unroll
        for (int i = 0; i < 8; i++) {
            int o = tid + i * 256;
            int oo = o & 1023;
            int row = oo >> 3, c = oo & 7;
            uint32_t off = sw128((uint32_t)(row * 128 + c * 16));
            if (o < 1024) {
                int sr = m0 + row; if (sr > M - 1) sr = M - 1;
                cp16(ab + off, A + (long long)sr * 512 + k0 + c * 8);
            } else {
                cp16(bb + off, W + (long long)(n0 + row) * 512 + k0 + c * 8);
            }
        }
    };

    load_stage(0); cp_commit();
    load_stage(1); cp_commit();

    const int a_row = (lane & 15);
    const int a_c16 = (lane >> 4);
    const int b_row = ((lane >> 4) << 3) + (lane & 7);
    const int b_c16 = ((lane >> 3) & 1);

    for (int s = 0; s < 8; s++) {
        cp_wait1();
        __syncthreads();
        const int buf = s % 3;
        const uint32_t ab = sb + buf * STAGE_BYTES;
        const uint32_t bb = ab + 16384;

#pragma unroll
        for (int ks = 0; ks < 4; ks++) {
            uint32_t af[4][4], bf[2][4];
#pragma unroll
            for (int mf = 0; mf < 4; mf++) {
                int m = wm * 64 + mf * 16 + a_row;
                ldm_x4(af[mf], ab + sw128((uint32_t)(m * 128 + ks * 32 + a_c16 * 16)));
            }
#pragma unroll
            for (int np = 0; np < 2; np++) {
                int n = wn * 32 + np * 16 + b_row;
                ldm_x4(bf[np], bb + sw128((uint32_t)(n * 128 + ks * 32 + b_c16 * 16)));
            }
#pragma unroll
            for (int mf = 0; mf < 4; mf++) {
                mma_fp16(acc[mf][0], af[mf][0], af[mf][1], af[mf][2], af[mf][3],
                         bf[0][0], bf[0][1]);
                mma_fp16(acc[mf][1], af[mf][0], af[mf][1], af[mf][2], af[mf][3],
                         bf[0][2], bf[0][3]);
                mma_fp16(acc[mf][2], af[mf][0], af[mf][1], af[mf][2], af[mf][3],
                         bf[1][0], bf[1][1]);
                mma_fp16(acc[mf][3], af[mf][0], af[mf][1], af[mf][2], af[mf][3],
                         bf[1][2], bf[1][3]);
            }
        }
        if (s + 2 < 8) load_stage(s + 2);
        cp_commit();
    }

#pragma unroll
    for (int mf = 0; mf < 4; mf++) {
#pragma unroll
        for (int h = 0; h < 2; h++) {
            int m = m0 + wm * 64 + mf * 16 + g + h * 8;
            if (m >= M) continue;
            long long orow;
            if (mode == 2) {
                int b_ = m / 3150, tq = (m / 50) % 63, i_ = m % 50;
                orow = ((long long)(b_ * 64 + tq + 1) * 50 + i_) * 512;
            } else {
                orow = (long long)m * 512;
            }
            long long arow = (long long)m * 512;
#pragma unroll
            for (int nf = 0; nf < 4; nf++) {
                int n = n0 + wn * 32 + nf * 8 + t * 2;
                float v0 = acc[mf][nf][h * 2 + 0];
                float v1 = acc[mf][nf][h * 2 + 1];
                float o0, o1;
                if (mode == 0) {
                    o0 = v0 + bias[n]; o1 = v1 + bias[n + 1];
                } else if (mode == 1) {
                    o0 = fmaxf(v0 + bias[n], 0.f);
                    o1 = fmaxf(v1 + bias[n + 1], 0.f);
                } else if (mode == 2) {
                    o0 = add2[orow + n]     + add1[arow + n]     + fmaxf(v0 + bias[n], 0.f);
                    o1 = add2[orow + n + 1] + add1[arow + n + 1] + fmaxf(v1 + bias[n + 1], 0.f);
                } else {
                    o0 = add1[arow + n]     + fmaxf(v0, 0.f);
                    o1 = add1[arow + n + 1] + fmaxf(v1, 0.f);
                }
                *(float2*)(C + orow + n) = make_float2(o0, o1);
                if (mode == 3)
                    *(__half2*)(Ch + orow + n) = __floats2half2_rn(o0, o1);
            }
        }
    }
}

// ---------------------------------------------------------------------------
// Sparse fused attention for one (b,t), 512 threads, pipelined reductions.
// Writes spatial = relu(LN(agg + x)) and the dense attention matrix.
// ---------------------------------------------------------------------------
#define ATTN_SMEM_FLOATS (50*512 + 3*512 + 50*52 + 6*52 + 8)

__global__ __launch_bounds__(512) void attn_kernel(
    const float* __restrict__ x, const float* __restrict__ edge,
    const float* __restrict__ lng, const float* __restrict__ lnb,
    float* __restrict__ spatial, float* __restrict__ attn_out)
{
    extern __shared__ float sm[];
    float* xs  = sm;               // [50][512]
    float* es  = xs + 50 * 512;    // [3][512]
    float* S   = es + 3 * 512;     // [50][52]
    float* rq  = S + 50 * 52;
    float* rk0 = rq + 52;
    float* rk1 = rk0 + 52;
    float* d0  = rk1 + 52;
    float* d1  = d0 + 52;
    float* d2  = d1 + 52;
    float* sc  = d2 + 52;

    const int bt = blockIdx.x;
    const int tid = threadIdx.x;
    const int wid = tid >> 5, lane = tid & 31;
    const float* xg = x + (long long)bt * 50 * 512;

    for (int idx = tid; idx < 50 * 128; idx += 512)
        ((float4*)xs)[idx] = ((const float4*)xg)[idx];
    for (int idx = tid; idx < 3 * 128; idx += 512)
        ((float4*)es)[idx] = ((const float4*)edge)[idx];
    __syncthreads();

    // ---- window dots: warp per row, 9 partials then 9 interleaved reduces
    for (int i = wid; i < 49; i += 16) {
        float4 ai[4];
        const float4* xi4 = (const float4*)(xs + i * 512) + lane * 4;
#pragma unroll
        for (int q = 0; q < 4; q++) ai[q] = xi4[q];
        int qr = i / 7, qc = i - qr * 7;
        int r0 = qr - 1; if (r0 < 0) r0 = 0;          // no upper clip (ref uses t=64)
        int c0 = qc - 1; if (c0 < 0) c0 = 0; if (c0 > 4) c0 = 4;
        float part[9];
#pragma unroll
        for (int a = 0; a < 3; a++) {
            int kr = r0 + a;
            int krc = kr > 6 ? 6 : kr;                // safe address; unused if kr>6
#pragma unroll
            for (int b = 0; b < 3; b++)
                part[a * 3 + b] = dot16(ai, xs + (krc * 7 + c0 + b) * 512, lane);
        }
#pragma unroll
        for (int q = 0; q < 9; q++) part[q] = wreduce(part[q]);
        if (lane == 0) {
#pragma unroll
            for (int a = 0; a < 3; a++) {
                int kr = r0 + a;
                if (kr <= 6) {
#pragma unroll
                    for (int b = 0; b < 3; b++)
                        S[i * 52 + kr * 7 + c0 + b] = part[a * 3 + b];
                }
            }
        }
    }

    // ---- row/col 49 dots: 4 batched per warp
    {
        float4 a49[4];
        const float4* x49 = (const float4*)(xs + 49 * 512) + lane * 4;
#pragma unroll
        for (int q = 0; q < 4; q++) a49[q] = x49[q];
        float part[4];
#pragma unroll
        for (int q = 0; q < 4; q++) {
            int j = wid + q * 16;
            int jc = j < 50 ? j : 49;
            part[q] = dot16(a49, xs + jc * 512, lane);
        }
#pragma unroll
        for (int q = 0; q < 4; q++) part[q] = wreduce(part[q]);
        if (lane == 0) {
#pragma unroll
            for (int q = 0; q < 4; q++) {
                int j = wid + q * 16;
                if (j < 50) { S[49 * 52 + j] = part[q]; S[j * 52 + 49] = part[q]; }
            }
        }
    }

    // ---- edge dots d_k[i] (3 interleaved reduces per row) and E_k
#pragma unroll
    for (int q = 0; q < 4; q++) {
        int i = wid + q * 16;
        if (i < 50) {
            float4 ai[4];
            const float4* xi4 = (const float4*)(xs + i * 512) + lane * 4;
#pragma unroll
            for (int p = 0; p < 4; p++) ai[p] = xi4[p];
            float p0 = dot16(ai, es, lane);
            float p1 = dot16(ai, es + 512, lane);
            float p2 = dot16(ai, es + 1024, lane);
            p0 = wreduce(p0); p1 = wreduce(p1); p2 = wreduce(p2);
            if (lane == 0) { d0[i] = p0; d1[i] = p1; d2[i] = p2; }
        }
    }
    if (wid < 3) {
        float4 ek[4];
        const float4* e4 = (const float4*)(es + wid * 512) + lane * 4;
#pragma unroll
        for (int q = 0; q < 4; q++) ek[q] = e4[q];
        float v = wreduce(dot16(ek, es + wid * 512, lane));
        if (lane == 0) sc[wid] = v;
    }
    __syncthreads();

    // ---- norms
    if (tid < 50) {
        float gd = S[tid * 53];
        rq[tid]  = 1.f / fmaxf(sqrtf(gd), 1e-12f);
        rk0[tid] = 1.f / fmaxf(sqrtf(gd + 2.f * d0[tid] + sc[0]), 1e-12f);
        rk1[tid] = 1.f / fmaxf(sqrtf(gd + 2.f * d1[tid] + sc[1]), 1e-12f);
    } else if (tid == 50) {
        sc[3] = 1.f / fmaxf(sqrtf(S[49 * 53] + 2.f * d2[49] + sc[2]), 1e-12f);
    }
    __syncthreads();

    const float rk2  = sc[3];
    const float d149 = d1[49];
    const float rq49 = rq[49];

    // ---- scores (dense, in place)
    for (int p = tid; p < 2500; p += 512) {
        int i = p / 50, j = p - i * 50;
        float v;
        if (i == j)        v = NEGBIG;
        else if (j == 49)  v = (S[i * 52 + 49] + d2[i]) * rq[i] * rk2;
        else if (i == 49)  v = (S[49 * 52 + j] + d149) * rq49 * rk1[j];
        else {
            int qr = i / 7, qc = i - qr * 7;
            int kr = j / 7, kc = j - kr * 7;
            int r0 = qr - 1; if (r0 < 0) r0 = 0;
            int c0 = qc - 1; if (c0 < 0) c0 = 0; if (c0 > 4) c0 = 4;
            bool ok = (kr >= r0) && (kr <= r0 + 2) && (kc >= c0) && (kc <= c0 + 2);
            v = ok ? (S[i * 52 + j] + d0[i]) * rq[i] * rk0[j] : NEGBIG;
        }
        S[i * 52 + j] = v;
    }
    __syncthreads();

    // ---- softmax: warp per row (lanes cover 50 cols in 2 chunks)
    for (int i = wid; i < 50; i += 16) {
        float* row = S + i * 52;
        float v0 = (lane < 50)      ? row[lane]      : -3.4e38f;
        float v1 = (lane + 32 < 50) ? row[lane + 32] : -3.4e38f;
        float mx = fmaxf(v0, v1);
#pragma unroll
        for (int o = 16; o; o >>= 1) mx = fmaxf(mx, __shfl_xor_sync(0xffffffffu, mx, o));
        float e0 = (lane < 50)      ? expf(v0 - mx) : 0.f;
        float e1 = (lane + 32 < 50) ? expf(v1 - mx) : 0.f;
        float s = wreduce(e0 + e1);
        float inv = 1.f / s;
        if (lane < 50)      row[lane]      = e0 * inv;
        if (lane + 32 < 50) row[lane + 32] = e1 * inv;
    }
    __syncthreads();

    // ---- write attention
    for (int p = tid; p < 2500; p += 512)
        attn_out[(long long)bt * 2500 + p] = S[(p / 50) * 52 + (p % 50)];

    // ---- sparse aggregation + residual + LN + relu
    for (int i = wid; i < 50; i += 16) {
        float4 acc[4];
#pragma unroll
        for (int q = 0; q < 4; q++) acc[q] = make_float4(0.f, 0.f, 0.f, 0.f);
        const float aL = S[i * 52 + 49];

        auto addj = [&](int j, float w) {
            const float4* xj = (const float4*)(xs + j * 512) + lane * 4;
#pragma unroll
            for (int q = 0; q < 4; q++) {
                float4 v = xj[q];
                acc[q].x += w * v.x; acc[q].y += w * v.y;
                acc[q].z += w * v.z; acc[q].w += w * v.w;
            }
        };

        if (i < 49) {
            int qr = i / 7, qc = i - qr * 7;
            int r0 = qr - 1; if (r0 < 0) r0 = 0;
            int c0 = qc - 1; if (c0 < 0) c0 = 0; if (c0 > 4) c0 = 4;
            for (int a = 0; a < 3; a++) {
                int kr = r0 + a;
                if (kr > 6) break;
                for (int b = 0; b < 3; b++) {
                    int j = kr * 7 + c0 + b;
                    addj(j, S[i * 52 + j]);
                }
            }
            addj(49, aL);
        } else {
            for (int j = 0; j < 49; j++) addj(j, S[49 * 52 + j]);
        }

        const float4* ese = (const float4*)(es + (i < 49 ? 0 : 512)) + lane * 4;
        const float4* e2v = (const float4*)(es + 1024) + lane * 4;
        const float4* xi4 = (const float4*)(xs + i * 512) + lane * 4;
        const float w1 = 1.f - aL;
        float4 y[4];
        float s1 = 0.f;
#pragma unroll
        for (int q = 0; q < 4; q++) {
            float4 e0q = ese[q], e2q = e2v[q], xq = xi4[q];
            y[q].x = acc[q].x + w1 * e0q.x + aL * e2q.x + xq.x;
            y[q].y = acc[q].y + w1 * e0q.y + aL * e2q.y + xq.y;
            y[q].z = acc[q].z + w1 * e0q.z + aL * e2q.z + xq.z;
            y[q].w = acc[q].w + w1 * e0q.w + aL * e2q.w + xq.w;
            s1 += y[q].x + y[q].y + y[q].z + y[q].w;
        }
        s1 = wreduce(s1);
        float mean = s1 * (1.f / 512.f);
        float s2 = 0.f;
#pragma unroll
        for (int q = 0; q < 4; q++) {
            float dx = y[q].x - mean, dy = y[q].y - mean;
            float dz = y[q].z - mean, dw = y[q].w - mean;
            s2 += dx * dx + dy * dy + dz * dz + dw * dw;
        }
        s2 = wreduce(s2);
        float inv = rsqrtf(s2 * (1.f / 512.f) + 1e-5f);

        const float4* gp = (const float4*)lng + lane * 4;
        const float4* bp = (const float4*)lnb + lane * 4;
        float4* op = (float4*)(spatial + ((long long)bt * 50 + i) * 512) + lane * 4;
#pragma unroll
        for (int q = 0; q < 4; q++) {
            float4 gv = gp[q], bv = bp[q], o;
            o.x = fmaxf((y[q].x - mean) * inv * gv.x + bv.x, 0.f);
            o.y = fmaxf((y[q].y - mean) * inv * gv.y + bv.y, 0.f);
            o.z = fmaxf((y[q].z - mean) * inv * gv.z + bv.z, 0.f);
            o.w = fmaxf((y[q].w - mean) * inv * gv.w + bv.w, 0.f);
            op[q] = o;
        }
    }
}

// ---------------------------------------------------------------------------
// LayerNorm (warp per 512-row); optional t=0 source override; half out.
// ---------------------------------------------------------------------------
__global__ __launch_bounds__(256) void ln_kernel(
    const float* __restrict__ in, const float* __restrict__ in0,
    float* __restrict__ outf, __half* __restrict__ outh,
    const float* __restrict__ g, const float* __restrict__ b,
    int rows, int do_relu)
{
    int warp = (blockIdx.x * 256 + threadIdx.x) >> 5;
    int lane = threadIdx.x & 31;
    if (warp >= rows) return;
    const float* src = in;
    if (in0) {
        int t = (warp / 50) & 63;
        if (t == 0) src = in0;
    }
    const float4* ip = (const float4*)(src + (long long)warp * 512);
    float4 v[4];
    float s = 0.f;
#pragma unroll
    for (int q = 0; q < 4; q++) {
        v[q] = ip[lane + 32 * q];
        s += v[q].x + v[q].y + v[q].z + v[q].w;
    }
#pragma unroll
    for (int off = 16; off; off >>= 1) s += __shfl_xor_sync(0xffffffffu, s, off);
    float mean = s * (1.f / 512.f);
    float ss = 0.f;
#pragma unroll
    for (int q = 0; q < 4; q++) {
        float dx = v[q].x - mean, dy = v[q].y - mean, dz = v[q].z - mean, dw = v[q].w - mean;
        ss += dx * dx + dy * dy + dz * dz + dw * dw;
    }
#pragma unroll
    for (int off = 16; off; off >>= 1) ss += __shfl_xor_sync(0xffffffffu, ss, off);
    float inv = rsqrtf(ss * (1.f / 512.f) + 1e-5f);
    const float4* gp = (const float4*)g;
    const float4* bp = (const float4*)b;
#pragma unroll
    for (int q = 0; q < 4; q++) {
        int c = lane + 32 * q;
        float4 gv = gp[c], bv = bp[c], o;
        o.x = (v[q].x - mean) * inv * gv.x + bv.x;
        o.y = (v[q].y - mean) * inv * gv.y + bv.y;
        o.z = (v[q].z - mean) * inv * gv.z + bv.z;
        o.w = (v[q].w - mean) * inv * gv.w + bv.w;
        if (do_relu) {
            o.x = fmaxf(o.x, 0.f); o.y = fmaxf(o.y, 0.f);
            o.z = fmaxf(o.z, 0.f); o.w = fmaxf(o.w, 0.f);
        }
        if (outf) ((float4*)(outf + (long long)warp * 512))[c] = o;
        if (outh) {
            __half2* hp = (__half2*)(outh + (long long)warp * 512);
            hp[c * 2 + 0] = __floats2half2_rn(o.x, o.y);
            hp[c * 2 + 1] = __floats2half2_rn(o.z, o.w);
        }
    }
}

// ---------------------------------------------------------------------------
// cos similarity + half GEMM inputs: hc = cos*prev, hs = (1-cos)*cur
// ---------------------------------------------------------------------------
__global__ __launch_bounds__(256) void cos_kernel(
    const float* __restrict__ spatial, float* __restrict__ cosv,
    __half* __restrict__ hc, __half* __restrict__ hs)
{
    int warp = (blockIdx.x * 256 + threadIdx.x) >> 5;
    int lane = threadIdx.x & 31;
    if (warp >= 50400) return;
    int i = warp % 50;
    int tq = (warp / 50) % 63;
    int b_ = warp / 3150;
    long long cur_off  = (((long long)b_ * 64 + tq + 1) * 50 + i) * 512;
    long long prev_off = (((long long)b_ * 64 + tq) * 50 + i) * 512;
    const float4* cp = (const float4*)(spatial + cur_off);
    const float4* pp = (const float4*)(spatial + prev_off);
    float4 cb[4], pb[4];
    float dt = 0.f, na = 0.f, nb = 0.f;
#pragma unroll
    for (int q = 0; q < 4; q++) {
        cb[q] = cp[lane + 32 * q];
        pb[q] = pp[lane + 32 * q];
        dt += cb[q].x * pb[q].x + cb[q].y * pb[q].y + cb[q].z * pb[q].z + cb[q].w * pb[q].w;
        na += cb[q].x * cb[q].x + cb[q].y * cb[q].y + cb[q].z * cb[q].z + cb[q].w * cb[q].w;
        nb += pb[q].x * pb[q].x + pb[q].y * pb[q].y + pb[q].z * pb[q].z + pb[q].w * pb[q].w;
    }
#pragma unroll
    for (int off = 16; off; off >>= 1) {
        dt += __shfl_xor_sync(0xffffffffu, dt, off);
        na += __shfl_xor_sync(0xffffffffu, na, off);
        nb += __shfl_xor_sync(0xffffffffu, nb, off);
    }
    float cv = dt / (fmaxf(sqrtf(na), 1e-8f) * fmaxf(sqrtf(nb), 1e-8f));
    if (lane == 0) cosv[warp] = cv;
    __half2* hcp = (__half2*)(hc + (long long)warp * 512);
    __half2* hsp = (__half2*)(hs + (long long)warp * 512);
    float w1 = 1.f - cv;
#pragma unroll
    for (int q = 0; q < 4; q++) {
        int c = lane + 32 * q;
        hcp[c * 2 + 0] = __floats2half2_rn(cv * pb[q].x, cv * pb[q].y);
        hcp[c * 2 + 1] = __floats2half2_rn(cv * pb[q].z, cv * pb[q].w);
        hsp[c * 2 + 0] = __floats2half2_rn(w1 * cb[q].x, w1 * cb[q].y);
        hsp[c * 2 + 1] = __floats2half2_rn(w1 * cb[q].z, w1 * cb[q].w);
    }
}

// ---------------------------------------------------------------------------
// Host launcher
// ---------------------------------------------------------------------------
extern "C" void kernel_launch(void* const* d_in, const int* in_sizes, int n_in,
                              void* d_out, int out_size)
{
    const float* visual = (const float*)d_in[0];
    const float* audio  = (const float*)d_in[1];
    const float* in_W   = (const float*)d_in[2];
    const float* in_b   = (const float*)d_in[3];
    const float* out_W  = (const float*)d_in[4];
    const float* out_b  = (const float*)d_in[5];

    float *node, *spatial, *t1, *t2, *attnb, *cosb;
    __half *hA, *hc, *hs, *ht3, *hnode, *wh;
    cudaGetSymbolAddress((void**)&node,    g_node);
    cudaGetSymbolAddress((void**)&spatial, g_spatial);
    cudaGetSymbolAddress((void**)&t1,      g_t1);
    cudaGetSymbolAddress((void**)&t2,      g_t2);
    cudaGetSymbolAddress((void**)&attnb,   g_attn);
    cudaGetSymbolAddress((void**)&cosb,    g_cos);
    cudaGetSymbolAddress((void**)&hA,      g_hA);
    cudaGetSymbolAddress((void**)&hc,      g_hc);
    cudaGetSymbolAddress((void**)&hs,      g_hs);
    cudaGetSymbolAddress((void**)&ht3,     g_ht3);
    cudaGetSymbolAddress((void**)&hnode,   g_hnode);
    cudaGetSymbolAddress((void**)&wh,      g_wh);

    const int smem_attn = ATTN_SMEM_FLOATS * 4;
    cudaFuncSetAttribute(attn_kernel,
                         cudaFuncAttributeMaxDynamicSharedMemorySize, smem_attn);
    cudaFuncSetAttribute(gemm_fp16,
                         cudaFuncAttributeMaxDynamicSharedMemorySize, GEMM_SMEM);

    wround8_kernel<<<2048, 256>>>(
        in_W, (const float*)d_in[9], (const float*)d_in[11], (const float*)d_in[13],
        (const float*)d_in[17], (const float*)d_in[19], (const float*)d_in[21], out_W,
        wh);

    concat_kernel<<<25600, 256>>>(visual, audio, hA);
    dim3 gAll(4, 400);
    dim3 gTmp(4, 394);
    gemm_fp16<<<gAll, 256, GEMM_SMEM>>>(hA, wh + 0 * 262144, in_b,
                                        nullptr, nullptr, node, nullptr,
                                        51200, 0);

    for (int L = 0; L < 2; L++) {
        int base = 6 + L * 8;
        const float* edge = (const float*)d_in[base + 0];
        const float* lng  = (const float*)d_in[base + 1];
        const float* lnb  = (const float*)d_in[base + 2];
        const float* bc   = (const float*)d_in[base + 4];
        const float* bs   = (const float*)d_in[base + 6];
        const __half* wc  = wh + (long long)(1 + L * 3) * 262144;
        const __half* ws  = wh + (long long)(2 + L * 3) * 262144;
        const __half* wo  = wh + (long long)(3 + L * 3) * 262144;

        attn_kernel<<<1024, 512, smem_attn>>>(node, edge, lng, lnb,
                                              spatial, attnb);
        cos_kernel<<<6300, 256>>>(spatial, cosb, hc, hs);
        gemm_fp16<<<gTmp, 256, GEMM_SMEM>>>(hc, wc, bc, nullptr, nullptr,
                                            t1, nullptr, 50400, 1);
        gemm_fp16<<<gTmp, 256, GEMM_SMEM>>>(hs, ws, bs, t1, spatial,
                                            t2, nullptr, 50400, 2);
        ln_kernel<<<6400, 256>>>(t2, spatial, nullptr, ht3, lng, lnb, 51200, 0);
        gemm_fp16<<<gAll, 256, GEMM_SMEM>>>(ht3, wo, nullptr, node, nullptr,
                                            node, hnode, 51200, 3);
    }

    gemm_fp16<<<gAll, 256, GEMM_SMEM>>>(hnode, wh + 7LL * 262144, out_b,
                                        nullptr, nullptr, (float*)d_out,
                                        nullptr, 51200, 0);

    long long need = OUT_ELEMS + ATTN_ELEMS + COS_ELEMS;
    if ((long long)out_size >= need) {
        cudaMemcpyAsync((float*)d_out + OUT_ELEMS, attnb,
                        ATTN_ELEMS * sizeof(float), cudaMemcpyDeviceToDevice);
        cudaMemcpyAsync((float*)d_out + OUT_ELEMS + ATTN_ELEMS, cosb,
                        COS_ELEMS * sizeof(float), cudaMemcpyDeviceToDevice);
    }
}

// round 10
// speedup vs baseline: 1.7614x; 1.3495x over previous
#include <cuda_runtime.h>
#include <cuda_fp16.h>
#include <cstdint>

// ---------------------------------------------------------------------------
// Problem: B=16, T=64, N=49(+1)=50 nodes, D=H=512, WIN=7
// ---------------------------------------------------------------------------
#define NEGBIG (-1e9f)

static const long long OUT_ELEMS  = 51200LL * 512;
static const long long ATTN_ELEMS = 1024LL * 2500;
static const long long COS_ELEMS  = 50400LL;

// ---------------------------------------------------------------------------
// Device scratch
// ---------------------------------------------------------------------------
__device__ float  g_node[51200 * 512];
__device__ float  g_spatial[51200 * 512];
__device__ float  g_t1[51200 * 512];
__device__ float  g_t2[51200 * 512];
__device__ float  g_attn[1024 * 2500];
__device__ float  g_cos[50400];
__device__ __half g_hA[51200 * 512];
__device__ __half g_hc[50400 * 512];
__device__ __half g_hs[50400 * 512];
__device__ __half g_ht3[51200 * 512];
__device__ __half g_hnode[51200 * 512];
__device__ __half g_wh[8 * 512 * 512];

// ---------------------------------------------------------------------------
// helpers
// ---------------------------------------------------------------------------
__device__ __forceinline__ uint32_t smem_u32(const void* p) {
    uint32_t a;
    asm("{ .reg .u64 t; cvta.to.shared.u64 t, %1; cvt.u32.u64 %0, t; }"
        : "=r"(a) : "l"(p));
    return a;
}
__device__ __forceinline__ uint32_t sw128(uint32_t off) {
    return off ^ ((off >> 3) & 0x70);
}
__device__ __forceinline__ void cp16(uint32_t dst, const void* src) {
    asm volatile("cp.async.cg.shared.global [%0], [%1], 16;\n"
                 :: "r"(dst), "l"(src));
}
__device__ __forceinline__ void cp_commit() {
    asm volatile("cp.async.commit_group;\n" ::: "memory");
}
__device__ __forceinline__ void cp_wait1() {
    asm volatile("cp.async.wait_group 1;\n" ::: "memory");
}
__device__ __forceinline__ void ldm_x4(uint32_t r[4], uint32_t addr) {
    asm volatile("ldmatrix.sync.aligned.m8n8.x4.shared.b16 {%0,%1,%2,%3}, [%4];"
                 : "=r"(r[0]), "=r"(r[1]), "=r"(r[2]), "=r"(r[3]) : "r"(addr));
}
__device__ __forceinline__ void mma_fp16(
    float c[4], uint32_t a0, uint32_t a1, uint32_t a2, uint32_t a3,
    uint32_t b0, uint32_t b1)
{
    asm volatile(
        "mma.sync.aligned.m16n8k16.row.col.f32.f16.f16.f32 "
        "{%0,%1,%2,%3}, {%4,%5,%6,%7}, {%8,%9}, {%0,%1,%2,%3};\n"
        : "+f"(c[0]), "+f"(c[1]), "+f"(c[2]), "+f"(c[3])
        : "r"(a0), "r"(a1), "r"(a2), "r"(a3), "r"(b0), "r"(b1));
}
__device__ __forceinline__ float wreduce(float s) {
#pragma unroll
    for (int o = 16; o; o >>= 1) s += __shfl_xor_sync(0xffffffffu, s, o);
    return s;
}
// per-lane partial dot, interleaved layout: lane handles float4 [q*32 + lane]
__device__ __forceinline__ float dot16i(const float4 a[4], const float* rb, int lane) {
    const float4* b4 = (const float4*)rb;
    float s = 0.f;
#pragma unroll
    for (int q = 0; q < 4; q++) {
        float4 b = b4[q * 32 + lane];
        s += a[q].x * b.x + a[q].y * b.y + a[q].z * b.z + a[q].w * b.w;
    }
    return s;
}

// ---------------------------------------------------------------------------
// all 8 weights -> half in one launch (grid 2048)
// ---------------------------------------------------------------------------
__global__ __launch_bounds__(256) void wround8_kernel(
    const float* s0, const float* s1, const float* s2, const float* s3,
    const float* s4, const float* s5, const float* s6, const float* s7,
    __half* __restrict__ dst)
{
    int w = blockIdx.x >> 8;
    const float* s =
        (w == 0) ? s0 : (w == 1) ? s1 : (w == 2) ? s2 : (w == 3) ? s3 :
        (w == 4) ? s4 : (w == 5) ? s5 : (w == 6) ? s6 : s7;
    __half2* d = (__half2*)(dst + (long long)w * 262144);
    int i = (blockIdx.x & 255) * 256 + threadIdx.x;
    float4 v = ((const float4*)s)[i];
    d[i * 2 + 0] = __floats2half2_rn(v.x, v.y);
    d[i * 2 + 1] = __floats2half2_rn(v.z, v.w);
}

// ---------------------------------------------------------------------------
// concat(visual, audio) -> half [51200, 512]
// ---------------------------------------------------------------------------
__global__ __launch_bounds__(256) void concat_kernel(
    const float* __restrict__ vis, const float* __restrict__ aud,
    __half* __restrict__ out)
{
    long long idx = (long long)blockIdx.x * 256 + threadIdx.x;
    if (idx >= (long long)51200 * 128) return;
    long long r = idx >> 7;
    int hv = (int)(idx & 127);
    int bt = (int)(r / 50), i = (int)(r % 50);
    float4 v;
    if (i < 49)
        v = ((const float4*)vis)[((long long)bt * 49 + i) * 128 + hv];
    else
        v = ((const float4*)aud)[(long long)bt * 128 + hv];
    __half2* d = (__half2*)out;
    d[idx * 2 + 0] = __floats2half2_rn(v.x, v.y);
    d[idx * 2 + 1] = __floats2half2_rn(v.z, v.w);
}

// ---------------------------------------------------------------------------
// fp16 tensor-core NT GEMM: CTA 128x128, k-tile 64, 3-stage cp.async,
// 256 threads / 8 warps, 2 CTAs/SM.
// ---------------------------------------------------------------------------
#define STAGE_BYTES 32768
#define GEMM_SMEM   (3 * STAGE_BYTES)

__global__ __launch_bounds__(256) void gemm_fp16(
    const __half* __restrict__ A, const __half* __restrict__ W,
    const float* __restrict__ bias, const float* __restrict__ add1,
    const float* __restrict__ add2, float* __restrict__ C,
    __half* __restrict__ Ch, int M, int mode)
{
    extern __shared__ char smem[];
    const uint32_t sb = smem_u32(smem);

    const int tid = threadIdx.x;
    const int wid = tid >> 5, lane = tid & 31;
    const int wm = wid >> 2, wn = wid & 3;
    const int g = lane >> 2, t = lane & 3;
    const int m0 = blockIdx.y * 128;
    const int n0 = blockIdx.x * 128;

    float acc[4][4][4];
#pragma unroll
    for (int mf = 0; mf < 4; mf++)
#pragma unroll
        for (int nf = 0; nf < 4; nf++)
#pragma unroll
            for (int q = 0; q < 4; q++) acc[mf][nf][q] = 0.f;

    auto load_stage = [&](int s) {
        const int buf = s % 3;
        const uint32_t ab = sb + buf * STAGE_BYTES;
        const uint32_t bb = ab + 16384;
        const int k0 = s * 64;
#pragma unroll
        for (int i = 0; i < 8; i++) {
            int o = tid + i * 256;
            int oo = o & 1023;
            int row = oo >> 3, c = oo & 7;
            uint32_t off = sw128((uint32_t)(row * 128 + c * 16));
            if (o < 1024) {
                int sr = m0 + row; if (sr > M - 1) sr = M - 1;
                cp16(ab + off, A + (long long)sr * 512 + k0 + c * 8);
            } else {
                cp16(bb + off, W + (long long)(n0 + row) * 512 + k0 + c * 8);
            }
        }
    };

    load_stage(0); cp_commit();
    load_stage(1); cp_commit();

    const int a_row = (lane & 15);
    const int a_c16 = (lane >> 4);
    const int b_row = ((lane >> 4) << 3) + (lane & 7);
    const int b_c16 = ((lane >> 3) & 1);

    for (int s = 0; s < 8; s++) {
        cp_wait1();
        __syncthreads();
        const int buf = s % 3;
        const uint32_t ab = sb + buf * STAGE_BYTES;
        const uint32_t bb = ab + 16384;

#pragma unroll
        for (int ks = 0; ks < 4; ks++) {
            uint32_t af[4][4], bf[2][4];
#pragma unroll
            for (int mf = 0; mf < 4; mf++) {
                int m = wm * 64 + mf * 16 + a_row;
                ldm_x4(af[mf], ab + sw128((uint32_t)(m * 128 + ks * 32 + a_c16 * 16)));
            }
#pragma unroll
            for (int np = 0; np < 2; np++) {
                int n = wn * 32 + np * 16 + b_row;
                ldm_x4(bf[np], bb + sw128((uint32_t)(n * 128 + ks * 32 + b_c16 * 16)));
            }
#pragma unroll
            for (int mf = 0; mf < 4; mf++) {
                mma_fp16(acc[mf][0], af[mf][0], af[mf][1], af[mf][2], af[mf][3],
                         bf[0][0], bf[0][1]);
                mma_fp16(acc[mf][1], af[mf][0], af[mf][1], af[mf][2], af[mf][3],
                         bf[0][2], bf[0][3]);
                mma_fp16(acc[mf][2], af[mf][0], af[mf][1], af[mf][2], af[mf][3],
                         bf[1][0], bf[1][1]);
                mma_fp16(acc[mf][3], af[mf][0], af[mf][1], af[mf][2], af[mf][3],
                         bf[1][2], bf[1][3]);
            }
        }
        if (s + 2 < 8) load_stage(s + 2);
        cp_commit();
    }

#pragma unroll
    for (int mf = 0; mf < 4; mf++) {
#pragma unroll
        for (int h = 0; h < 2; h++) {
            int m = m0 + wm * 64 + mf * 16 + g + h * 8;
            if (m >= M) continue;
            long long orow;
            if (mode == 2) {
                int b_ = m / 3150, tq = (m / 50) % 63, i_ = m % 50;
                orow = ((long long)(b_ * 64 + tq + 1) * 50 + i_) * 512;
            } else {
                orow = (long long)m * 512;
            }
            long long arow = (long long)m * 512;
#pragma unroll
            for (int nf = 0; nf < 4; nf++) {
                int n = n0 + wn * 32 + nf * 8 + t * 2;
                float v0 = acc[mf][nf][h * 2 + 0];
                float v1 = acc[mf][nf][h * 2 + 1];
                float o0, o1;
                if (mode == 0) {
                    o0 = v0 + bias[n]; o1 = v1 + bias[n + 1];
                } else if (mode == 1) {
                    o0 = fmaxf(v0 + bias[n], 0.f);
                    o1 = fmaxf(v1 + bias[n + 1], 0.f);
                } else if (mode == 2) {
                    o0 = add2[orow + n]     + add1[arow + n]     + fmaxf(v0 + bias[n], 0.f);
                    o1 = add2[orow + n + 1] + add1[arow + n + 1] + fmaxf(v1 + bias[n + 1], 0.f);
                } else {
                    o0 = add1[arow + n]     + fmaxf(v0, 0.f);
                    o1 = add1[arow + n + 1] + fmaxf(v1, 0.f);
                }
                *(float2*)(C + orow + n) = make_float2(o0, o1);
                if (mode == 3)
                    *(__half2*)(Ch + orow + n) = __floats2half2_rn(o0, o1);
            }
        }
    }
}

// ---------------------------------------------------------------------------
// Sparse fused attention, 512 threads, conflict-free interleaved layout.
// Writes spatial = relu(LN(agg + x)) and the dense attention matrix.
// ---------------------------------------------------------------------------
#define ATTN_SMEM_FLOATS (50*512 + 3*512 + 50*52 + 6*52 + 8)

__global__ __launch_bounds__(512) void attn_kernel(
    const float* __restrict__ x, const float* __restrict__ edge,
    const float* __restrict__ lng, const float* __restrict__ lnb,
    float* __restrict__ spatial, float* __restrict__ attn_out)
{
    extern __shared__ float sm[];
    float* xs  = sm;               // [50][512]
    float* es  = xs + 50 * 512;    // [3][512]
    float* S   = es + 3 * 512;     // [50][52]
    float* rq  = S + 50 * 52;
    float* rk0 = rq + 52;
    float* rk1 = rk0 + 52;
    float* d0  = rk1 + 52;
    float* d1  = d0 + 52;
    float* d2  = d1 + 52;
    float* sc  = d2 + 52;

    const int bt = blockIdx.x;
    const int tid = threadIdx.x;
    const int wid = tid >> 5, lane = tid & 31;
    const float* xg = x + (long long)bt * 50 * 512;

    for (int idx = tid; idx < 50 * 128; idx += 512)
        ((float4*)xs)[idx] = ((const float4*)xg)[idx];
    for (int idx = tid; idx < 3 * 128; idx += 512)
        ((float4*)es)[idx] = ((const float4*)edge)[idx];
    __syncthreads();

    // ---- window dots: warp per row, 9 partials then 9 interleaved reduces
    for (int i = wid; i < 49; i += 16) {
        float4 ai[4];
        const float4* xi4 = (const float4*)(xs + i * 512);
#pragma unroll
        for (int q = 0; q < 4; q++) ai[q] = xi4[q * 32 + lane];
        int qr = i / 7, qc = i - qr * 7;
        int r0 = qr - 1; if (r0 < 0) r0 = 0;
        int c0 = qc - 1; if (c0 < 0) c0 = 0; if (c0 > 4) c0 = 4;
        float part[9];
#pragma unroll
        for (int a = 0; a < 3; a++) {
            int kr = r0 + a;
            int krc = kr > 6 ? 6 : kr;
#pragma unroll
            for (int b = 0; b < 3; b++)
                part[a * 3 + b] = dot16i(ai, xs + (krc * 7 + c0 + b) * 512, lane);
        }
#pragma unroll
        for (int q = 0; q < 9; q++) part[q] = wreduce(part[q]);
        if (lane == 0) {
#pragma unroll
            for (int a = 0; a < 3; a++) {
                int kr = r0 + a;
                if (kr <= 6) {
#pragma unroll
                    for (int b = 0; b < 3; b++)
                        S[i * 52 + kr * 7 + c0 + b] = part[a * 3 + b];
                }
            }
        }
    }

    // ---- row/col 49 dots: 4 batched per warp
    {
        float4 a49[4];
        const float4* x49 = (const float4*)(xs + 49 * 512);
#pragma unroll
        for (int q = 0; q < 4; q++) a49[q] = x49[q * 32 + lane];
        float part[4];
#pragma unroll
        for (int q = 0; q < 4; q++) {
            int j = wid + q * 16;
            int jc = j < 50 ? j : 49;
            part[q] = dot16i(a49, xs + jc * 512, lane);
        }
#pragma unroll
        for (int q = 0; q < 4; q++) part[q] = wreduce(part[q]);
        if (lane == 0) {
#pragma unroll
            for (int q = 0; q < 4; q++) {
                int j = wid + q * 16;
                if (j < 50) { S[49 * 52 + j] = part[q]; S[j * 52 + 49] = part[q]; }
            }
        }
    }

    // ---- edge dots d_k[i] and E_k
#pragma unroll
    for (int q = 0; q < 4; q++) {
        int i = wid + q * 16;
        if (i < 50) {
            float4 ai[4];
            const float4* xi4 = (const float4*)(xs + i * 512);
#pragma unroll
            for (int p = 0; p < 4; p++) ai[p] = xi4[p * 32 + lane];
            float p0 = dot16i(ai, es, lane);
            float p1 = dot16i(ai, es + 512, lane);
            float p2 = dot16i(ai, es + 1024, lane);
            p0 = wreduce(p0); p1 = wreduce(p1); p2 = wreduce(p2);
            if (lane == 0) { d0[i] = p0; d1[i] = p1; d2[i] = p2; }
        }
    }
    if (wid < 3) {
        float4 ek[4];
        const float4* e4 = (const float4*)(es + wid * 512);
#pragma unroll
        for (int q = 0; q < 4; q++) ek[q] = e4[q * 32 + lane];
        float v = wreduce(dot16i(ek, es + wid * 512, lane));
        if (lane == 0) sc[wid] = v;
    }
    __syncthreads();

    // ---- norms
    if (tid < 50) {
        float gd = S[tid * 53];
        rq[tid]  = 1.f / fmaxf(sqrtf(gd), 1e-12f);
        rk0[tid] = 1.f / fmaxf(sqrtf(gd + 2.f * d0[tid] + sc[0]), 1e-12f);
        rk1[tid] = 1.f / fmaxf(sqrtf(gd + 2.f * d1[tid] + sc[1]), 1e-12f);
    } else if (tid == 50) {
        sc[3] = 1.f / fmaxf(sqrtf(S[49 * 53] + 2.f * d2[49] + sc[2]), 1e-12f);
    }
    __syncthreads();

    const float rk2  = sc[3];
    const float d149 = d1[49];
    const float rq49 = rq[49];

    // ---- scores (dense, in place)
    for (int p = tid; p < 2500; p += 512) {
        int i = p / 50, j = p - i * 50;
        float v;
        if (i == j)        v = NEGBIG;
        else if (j == 49)  v = (S[i * 52 + 49] + d2[i]) * rq[i] * rk2;
        else if (i == 49)  v = (S[49 * 52 + j] + d149) * rq49 * rk1[j];
        else {
            int qr = i / 7, qc = i - qr * 7;
            int kr = j / 7, kc = j - kr * 7;
            int r0 = qr - 1; if (r0 < 0) r0 = 0;
            int c0 = qc - 1; if (c0 < 0) c0 = 0; if (c0 > 4) c0 = 4;
            bool ok = (kr >= r0) && (kr <= r0 + 2) && (kc >= c0) && (kc <= c0 + 2);
            v = ok ? (S[i * 52 + j] + d0[i]) * rq[i] * rk0[j] : NEGBIG;
        }
        S[i * 52 + j] = v;
    }
    __syncthreads();

    // ---- softmax: warp per row
    for (int i = wid; i < 50; i += 16) {
        float* row = S + i * 52;
        float v0 = (lane < 50)      ? row[lane]      : -3.4e38f;
        float v1 = (lane + 32 < 50) ? row[lane + 32] : -3.4e38f;
        float mx = fmaxf(v0, v1);
#pragma unroll
        for (int o = 16; o; o >>= 1) mx = fmaxf(mx, __shfl_xor_sync(0xffffffffu, mx, o));
        float e0 = (lane < 50)      ? expf(v0 - mx) : 0.f;
        float e1 = (lane + 32 < 50) ? expf(v1 - mx) : 0.f;
        float s = wreduce(e0 + e1);
        float inv = 1.f / s;
        if (lane < 50)      row[lane]      = e0 * inv;
        if (lane + 32 < 50) row[lane + 32] = e1 * inv;
    }
    __syncthreads();

    // ---- write attention
    for (int p = tid; p < 2500; p += 512)
        attn_out[(long long)bt * 2500 + p] = S[(p / 50) * 52 + (p % 50)];

    // ---- sparse aggregation + residual + LN + relu (interleaved layout)
    for (int i = wid; i < 50; i += 16) {
        float4 acc[4];
#pragma unroll
        for (int q = 0; q < 4; q++) acc[q] = make_float4(0.f, 0.f, 0.f, 0.f);
        const float aL = S[i * 52 + 49];

        auto addj = [&](int j, float w) {
            const float4* xj = (const float4*)(xs + j * 512);
#pragma unroll
            for (int q = 0; q < 4; q++) {
                float4 v = xj[q * 32 + lane];
                acc[q].x += w * v.x; acc[q].y += w * v.y;
                acc[q].z += w * v.z; acc[q].w += w * v.w;
            }
        };

        if (i < 49) {
            int qr = i / 7, qc = i - qr * 7;
            int r0 = qr - 1; if (r0 < 0) r0 = 0;
            int c0 = qc - 1; if (c0 < 0) c0 = 0; if (c0 > 4) c0 = 4;
            for (int a = 0; a < 3; a++) {
                int kr = r0 + a;
                if (kr > 6) break;
                for (int b = 0; b < 3; b++) {
                    int j = kr * 7 + c0 + b;
                    addj(j, S[i * 52 + j]);
                }
            }
            addj(49, aL);
        } else {
            for (int j = 0; j < 49; j++) addj(j, S[49 * 52 + j]);
        }

        const float4* ese = (const float4*)(es + (i < 49 ? 0 : 512));
        const float4* e2v = (const float4*)(es + 1024);
        const float4* xi4 = (const float4*)(xs + i * 512);
        const float w1 = 1.f - aL;
        float4 y[4];
        float s1 = 0.f;
#pragma unroll
        for (int q = 0; q < 4; q++) {
            int c = q * 32 + lane;
            float4 e0q = ese[c], e2q = e2v[c], xq = xi4[c];
            y[q].x = acc[q].x + w1 * e0q.x + aL * e2q.x + xq.x;
            y[q].y = acc[q].y + w1 * e0q.y + aL * e2q.y + xq.y;
            y[q].z = acc[q].z + w1 * e0q.z + aL * e2q.z + xq.z;
            y[q].w = acc[q].w + w1 * e0q.w + aL * e2q.w + xq.w;
            s1 += y[q].x + y[q].y + y[q].z + y[q].w;
        }
        s1 = wreduce(s1);
        float mean = s1 * (1.f / 512.f);
        float s2 = 0.f;
#pragma unroll
        for (int q = 0; q < 4; q++) {
            float dx = y[q].x - mean, dy = y[q].y - mean;
            float dz = y[q].z - mean, dw = y[q].w - mean;
            s2 += dx * dx + dy * dy + dz * dz + dw * dw;
        }
        s2 = wreduce(s2);
        float inv = rsqrtf(s2 * (1.f / 512.f) + 1e-5f);

        const float4* gp = (const float4*)lng;
        const float4* bp = (const float4*)lnb;
        float4* op = (float4*)(spatial + ((long long)bt * 50 + i) * 512);
#pragma unroll
        for (int q = 0; q < 4; q++) {
            int c = q * 32 + lane;
            float4 gv = gp[c], bv = bp[c], o;
            o.x = fmaxf((y[q].x - mean) * inv * gv.x + bv.x, 0.f);
            o.y = fmaxf((y[q].y - mean) * inv * gv.y + bv.y, 0.f);
            o.z = fmaxf((y[q].z - mean) * inv * gv.z + bv.z, 0.f);
            o.w = fmaxf((y[q].w - mean) * inv * gv.w + bv.w, 0.f);
            op[c] = o;
        }
    }
}

// ---------------------------------------------------------------------------
// LayerNorm (warp per 512-row); optional t=0 source override; half out.
// ---------------------------------------------------------------------------
__global__ __launch_bounds__(256) void ln_kernel(
    const float* __restrict__ in, const float* __restrict__ in0,
    float* __restrict__ outf, __half* __restrict__ outh,
    const float* __restrict__ g, const float* __restrict__ b,
    int rows, int do_relu)
{
    int warp = (blockIdx.x * 256 + threadIdx.x) >> 5;
    int lane = threadIdx.x & 31;
    if (warp >= rows) return;
    const float* src = in;
    if (in0) {
        int t = (warp / 50) & 63;
        if (t == 0) src = in0;
    }
    const float4* ip = (const float4*)(src + (long long)warp * 512);
    float4 v[4];
    float s = 0.f;
#pragma unroll
    for (int q = 0; q < 4; q++) {
        v[q] = ip[lane + 32 * q];
        s += v[q].x + v[q].y + v[q].z + v[q].w;
    }
#pragma unroll
    for (int off = 16; off; off >>= 1) s += __shfl_xor_sync(0xffffffffu, s, off);
    float mean = s * (1.f / 512.f);
    float ss = 0.f;
#pragma unroll
    for (int q = 0; q < 4; q++) {
        float dx = v[q].x - mean, dy = v[q].y - mean, dz = v[q].z - mean, dw = v[q].w - mean;
        ss += dx * dx + dy * dy + dz * dz + dw * dw;
    }
#pragma unroll
    for (int off = 16; off; off >>= 1) ss += __shfl_xor_sync(0xffffffffu, ss, off);
    float inv = rsqrtf(ss * (1.f / 512.f) + 1e-5f);
    const float4* gp = (const float4*)g;
    const float4* bp = (const float4*)b;
#pragma unroll
    for (int q = 0; q < 4; q++) {
        int c = lane + 32 * q;
        float4 gv = gp[c], bv = bp[c], o;
        o.x = (v[q].x - mean) * inv * gv.x + bv.x;
        o.y = (v[q].y - mean) * inv * gv.y + bv.y;
        o.z = (v[q].z - mean) * inv * gv.z + bv.z;
        o.w = (v[q].w - mean) * inv * gv.w + bv.w;
        if (do_relu) {
            o.x = fmaxf(o.x, 0.f); o.y = fmaxf(o.y, 0.f);
            o.z = fmaxf(o.z, 0.f); o.w = fmaxf(o.w, 0.f);
        }
        if (outf) ((float4*)(outf + (long long)warp * 512))[c] = o;
        if (outh) {
            __half2* hp = (__half2*)(outh + (long long)warp * 512);
            hp[c * 2 + 0] = __floats2half2_rn(o.x, o.y);
            hp[c * 2 + 1] = __floats2half2_rn(o.z, o.w);
        }
    }
}

// ---------------------------------------------------------------------------
// cos similarity + half GEMM inputs: hc = cos*prev, hs = (1-cos)*cur
// ---------------------------------------------------------------------------
__global__ __launch_bounds__(256) void cos_kernel(
    const float* __restrict__ spatial, float* __restrict__ cosv,
    __half* __restrict__ hc, __half* __restrict__ hs)
{
    int warp = (blockIdx.x * 256 + threadIdx.x) >> 5;
    int lane = threadIdx.x & 31;
    if (warp >= 50400) return;
    int i = warp % 50;
    int tq = (warp / 50) % 63;
    int b_ = warp / 3150;
    long long cur_off  = (((long long)b_ * 64 + tq + 1) * 50 + i) * 512;
    long long prev_off = (((long long)b_ * 64 + tq) * 50 + i) * 512;
    const float4* cp = (const float4*)(spatial + cur_off);
    const float4* pp = (const float4*)(spatial + prev_off);
    float4 cb[4], pb[4];
    float dt = 0.f, na = 0.f, nb = 0.f;
#pragma unroll
    for (int q = 0; q < 4; q++) {
        cb[q] = cp[lane + 32 * q];
        pb[q] = pp[lane + 32 * q];
        dt += cb[q].x * pb[q].x + cb[q].y * pb[q].y + cb[q].z * pb[q].z + cb[q].w * pb[q].w;
        na += cb[q].x * cb[q].x + cb[q].y * cb[q].y + cb[q].z * cb[q].z + cb[q].w * cb[q].w;
        nb += pb[q].x * pb[q].x + pb[q].y * pb[q].y + pb[q].z * pb[q].z + pb[q].w * pb[q].w;
    }
#pragma unroll
    for (int off = 16; off; off >>= 1) {
        dt += __shfl_xor_sync(0xffffffffu, dt, off);
        na += __shfl_xor_sync(0xffffffffu, na, off);
        nb += __shfl_xor_sync(0xffffffffu, nb, off);
    }
    float cv = dt / (fmaxf(sqrtf(na), 1e-8f) * fmaxf(sqrtf(nb), 1e-8f));
    if (lane == 0) cosv[warp] = cv;
    __half2* hcp = (__half2*)(hc + (long long)warp * 512);
    __half2* hsp = (__half2*)(hs + (long long)warp * 512);
    float w1 = 1.f - cv;
#pragma unroll
    for (int q = 0; q < 4; q++) {
        int c = lane + 32 * q;
        hcp[c * 2 + 0] = __floats2half2_rn(cv * pb[q].x, cv * pb[q].y);
        hcp[c * 2 + 1] = __floats2half2_rn(cv * pb[q].z, cv * pb[q].w);
        hsp[c * 2 + 0] = __floats2half2_rn(w1 * cb[q].x, w1 * cb[q].y);
        hsp[c * 2 + 1] = __floats2half2_rn(w1 * cb[q].z, w1 * cb[q].w);
    }
}

// ---------------------------------------------------------------------------
// Host launcher
// ---------------------------------------------------------------------------
extern "C" void kernel_launch(void* const* d_in, const int* in_sizes, int n_in,
                              void* d_out, int out_size)
{
    const float* visual = (const float*)d_in[0];
    const float* audio  = (const float*)d_in[1];
    const float* in_W   = (const float*)d_in[2];
    const float* in_b   = (const float*)d_in[3];
    const float* out_W  = (const float*)d_in[4];
    const float* out_b  = (const float*)d_in[5];

    float *node, *spatial, *t1, *t2, *attnb, *cosb;
    __half *hA, *hc, *hs, *ht3, *hnode, *wh;
    cudaGetSymbolAddress((void**)&node,    g_node);
    cudaGetSymbolAddress((void**)&spatial, g_spatial);
    cudaGetSymbolAddress((void**)&t1,      g_t1);
    cudaGetSymbolAddress((void**)&t2,      g_t2);
    cudaGetSymbolAddress((void**)&attnb,   g_attn);
    cudaGetSymbolAddress((void**)&cosb,    g_cos);
    cudaGetSymbolAddress((void**)&hA,      g_hA);
    cudaGetSymbolAddress((void**)&hc,      g_hc);
    cudaGetSymbolAddress((void**)&hs,      g_hs);
    cudaGetSymbolAddress((void**)&ht3,     g_ht3);
    cudaGetSymbolAddress((void**)&hnode,   g_hnode);
    cudaGetSymbolAddress((void**)&wh,      g_wh);

    const int smem_attn = ATTN_SMEM_FLOATS * 4;
    cudaFuncSetAttribute(attn_kernel,
                         cudaFuncAttributeMaxDynamicSharedMemorySize, smem_attn);
    cudaFuncSetAttribute(gemm_fp16,
                         cudaFuncAttributeMaxDynamicSharedMemorySize, GEMM_SMEM);

    wround8_kernel<<<2048, 256>>>(
        in_W, (const float*)d_in[9], (const float*)d_in[11], (const float*)d_in[13],
        (const float*)d_in[17], (const float*)d_in[19], (const float*)d_in[21], out_W,
        wh);

    concat_kernel<<<25600, 256>>>(visual, audio, hA);
    dim3 gAll(4, 400);
    dim3 gTmp(4, 394);
    gemm_fp16<<<gAll, 256, GEMM_SMEM>>>(hA, wh + 0 * 262144, in_b,
                                        nullptr, nullptr, node, nullptr,
                                        51200, 0);

    for (int L = 0; L < 2; L++) {
        int base = 6 + L * 8;
        const float* edge = (const float*)d_in[base + 0];
        const float* lng  = (const float*)d_in[base + 1];
        const float* lnb  = (const float*)d_in[base + 2];
        const float* bc   = (const float*)d_in[base + 4];
        const float* bs   = (const float*)d_in[base + 6];
        const __half* wc  = wh + (long long)(1 + L * 3) * 262144;
        const __half* ws  = wh + (long long)(2 + L * 3) * 262144;
        const __half* wo  = wh + (long long)(3 + L * 3) * 262144;

        attn_kernel<<<1024, 512, smem_attn>>>(node, edge, lng, lnb,
                                              spatial, attnb);
        cos_kernel<<<6300, 256>>>(spatial, cosb, hc, hs);
        gemm_fp16<<<gTmp, 256, GEMM_SMEM>>>(hc, wc, bc, nullptr, nullptr,
                                            t1, nullptr, 50400, 1);
        gemm_fp16<<<gTmp, 256, GEMM_SMEM>>>(hs, ws, bs, t1, spatial,
                                            t2, nullptr, 50400, 2);
        ln_kernel<<<6400, 256>>>(t2, spatial, nullptr, ht3, lng, lnb, 51200, 0);
        gemm_fp16<<<gAll, 256, GEMM_SMEM>>>(ht3, wo, nullptr, node, nullptr,
                                            node, hnode, 51200, 3);
    }

    gemm_fp16<<<gAll, 256, GEMM_SMEM>>>(hnode, wh + 7LL * 262144, out_b,
                                        nullptr, nullptr, (float*)d_out,
                                        nullptr, 51200, 0);

    long long need = OUT_ELEMS + ATTN_ELEMS + COS_ELEMS;
    if ((long long)out_size >= need) {
        cudaMemcpyAsync((float*)d_out + OUT_ELEMS, attnb,
                        ATTN_ELEMS * sizeof(float), cudaMemcpyDeviceToDevice);
        cudaMemcpyAsync((float*)d_out + OUT_ELEMS + ATTN_ELEMS, cosb,
                        COS_ELEMS * sizeof(float), cudaMemcpyDeviceToDevice);
    }
}

// round 12
// speedup vs baseline: 1.8495x; 1.0500x over previous
#include <cuda_runtime.h>
#include <cuda_fp16.h>
#include <cstdint>

// ---------------------------------------------------------------------------
// Problem: B=16, T=64, N=49(+1)=50 nodes, D=H=512, WIN=7
// ---------------------------------------------------------------------------
#define NEGBIG (-1e9f)

static const long long OUT_ELEMS  = 51200LL * 512;
static const long long ATTN_ELEMS = 1024LL * 2500;
static const long long COS_ELEMS  = 50400LL;

// ---------------------------------------------------------------------------
// Device scratch
// ---------------------------------------------------------------------------
__device__ float  g_node[51200 * 512];
__device__ float  g_spatial[51200 * 512];
__device__ float  g_t1[51200 * 512];
__device__ float  g_t2[51200 * 512];
__device__ float  g_attn[1024 * 2500];
__device__ float  g_cos[50400];
__device__ __half g_hA[51200 * 512];
__device__ __half g_hc[50400 * 512];
__device__ __half g_hs[50400 * 512];
__device__ __half g_ht3[51200 * 512];
__device__ __half g_hnode[51200 * 512];
__device__ __half g_wh[8 * 512 * 512];

// ---------------------------------------------------------------------------
// helpers
// ---------------------------------------------------------------------------
__device__ __forceinline__ uint32_t smem_u32(const void* p) {
    uint32_t a;
    asm("{ .reg .u64 t; cvta.to.shared.u64 t, %1; cvt.u32.u64 %0, t; }"
        : "=r"(a) : "l"(p));
    return a;
}
__device__ __forceinline__ uint32_t sw128(uint32_t off) {
    return off ^ ((off >> 3) & 0x70);
}
__device__ __forceinline__ void cp16(uint32_t dst, const void* src) {
    asm volatile("cp.async.cg.shared.global [%0], [%1], 16;\n"
                 :: "r"(dst), "l"(src));
}
__device__ __forceinline__ void cp_commit() {
    asm volatile("cp.async.commit_group;\n" ::: "memory");
}
__device__ __forceinline__ void cp_wait1() {
    asm volatile("cp.async.wait_group 1;\n" ::: "memory");
}
__device__ __forceinline__ void ldm_x4(uint32_t r[4], uint32_t addr) {
    asm volatile("ldmatrix.sync.aligned.m8n8.x4.shared.b16 {%0,%1,%2,%3}, [%4];"
                 : "=r"(r[0]), "=r"(r[1]), "=r"(r[2]), "=r"(r[3]) : "r"(addr));
}
__device__ __forceinline__ void mma_fp16(
    float c[4], uint32_t a0, uint32_t a1, uint32_t a2, uint32_t a3,
    uint32_t b0, uint32_t b1)
{
    asm volatile(
        "mma.sync.aligned.m16n8k16.row.col.f32.f16.f16.f32 "
        "{%0,%1,%2,%3}, {%4,%5,%6,%7}, {%8,%9}, {%0,%1,%2,%3};\n"
        : "+f"(c[0]), "+f"(c[1]), "+f"(c[2]), "+f"(c[3])
        : "r"(a0), "r"(a1), "r"(a2), "r"(a3), "r"(b0), "r"(b1));
}
__device__ __forceinline__ float wreduce(float s) {
#pragma unroll
    for (int o = 16; o; o >>= 1) s += __shfl_xor_sync(0xffffffffu, s, o);
    return s;
}
// lane owns 16 halves of a 512-elem row: uint4 [lane] and [lane+32].
__device__ __forceinline__ void ldcvt16(float2 a[8], const __half2* row, int lane) {
    const uint4* r4 = (const uint4*)row;
    uint4 u0 = r4[lane];
    uint4 u1 = r4[lane + 32];
    const __half2* h0 = (const __half2*)&u0;
    const __half2* h1 = (const __half2*)&u1;
#pragma unroll
    for (int k = 0; k < 4; k++) {
        a[k]     = __half22float2(h0[k]);
        a[4 + k] = __half22float2(h1[k]);
    }
}
// partial dot against converted a[8] (same ownership)
__device__ __forceinline__ float dot16h(const float2 a[8], const __half2* row, int lane) {
    const uint4* r4 = (const uint4*)row;
    uint4 u0 = r4[lane];
    uint4 u1 = r4[lane + 32];
    const __half2* h0 = (const __half2*)&u0;
    const __half2* h1 = (const __half2*)&u1;
    float s = 0.f;
#pragma unroll
    for (int k = 0; k < 4; k++) {
        float2 b0 = __half22float2(h0[k]);
        float2 b1 = __half22float2(h1[k]);
        s += a[k].x * b0.x + a[k].y * b0.y;
        s += a[4 + k].x * b1.x + a[4 + k].y * b1.y;
    }
    return s;
}

// ---------------------------------------------------------------------------
// all 8 weights -> half in one launch (grid 2048)
// ---------------------------------------------------------------------------
__global__ __launch_bounds__(256) void wround8_kernel(
    const float* s0, const float* s1, const float* s2, const float* s3,
    const float* s4, const float* s5, const float* s6, const float* s7,
    __half* __restrict__ dst)
{
    int w = blockIdx.x >> 8;
    const float* s =
        (w == 0) ? s0 : (w == 1) ? s1 : (w == 2) ? s2 : (w == 3) ? s3 :
        (w == 4) ? s4 : (w == 5) ? s5 : (w == 6) ? s6 : s7;
    __half2* d = (__half2*)(dst + (long long)w * 262144);
    int i = (blockIdx.x & 255) * 256 + threadIdx.x;
    float4 v = ((const float4*)s)[i];
    d[i * 2 + 0] = __floats2half2_rn(v.x, v.y);
    d[i * 2 + 1] = __floats2half2_rn(v.z, v.w);
}

// ---------------------------------------------------------------------------
// concat(visual, audio) -> half [51200, 512]
// ---------------------------------------------------------------------------
__global__ __launch_bounds__(256) void concat_kernel(
    const float* __restrict__ vis, const float* __restrict__ aud,
    __half* __restrict__ out)
{
    long long idx = (long long)blockIdx.x * 256 + threadIdx.x;
    if (idx >= (long long)51200 * 128) return;
    long long r = idx >> 7;
    int hv = (int)(idx & 127);
    int bt = (int)(r / 50), i = (int)(r % 50);
    float4 v;
    if (i < 49)
        v = ((const float4*)vis)[((long long)bt * 49 + i) * 128 + hv];
    else
        v = ((const float4*)aud)[(long long)bt * 128 + hv];
    __half2* d = (__half2*)out;
    d[idx * 2 + 0] = __floats2half2_rn(v.x, v.y);
    d[idx * 2 + 1] = __floats2half2_rn(v.z, v.w);
}

// ---------------------------------------------------------------------------
// fp16 tensor-core NT GEMM: CTA 128x128, k-tile 64, 3-stage cp.async,
// 256 threads / 8 warps. Ch mirror written whenever non-null.
// ---------------------------------------------------------------------------
#define STAGE_BYTES 32768
#define GEMM_SMEM   (3 * STAGE_BYTES)

__global__ __launch_bounds__(256) void gemm_fp16(
    const __half* __restrict__ A, const __half* __restrict__ W,
    const float* __restrict__ bias, const float* __restrict__ add1,
    const float* __restrict__ add2, float* __restrict__ C,
    __half* __restrict__ Ch, int M, int mode)
{
    extern __shared__ char smem[];
    const uint32_t sb = smem_u32(smem);

    const int tid = threadIdx.x;
    const int wid = tid >> 5, lane = tid & 31;
    const int wm = wid >> 2, wn = wid & 3;
    const int g = lane >> 2, t = lane & 3;
    const int m0 = blockIdx.y * 128;
    const int n0 = blockIdx.x * 128;

    float acc[4][4][4];
#pragma unroll
    for (int mf = 0; mf < 4; mf++)
#pragma unroll
        for (int nf = 0; nf < 4; nf++)
#pragma unroll
            for (int q = 0; q < 4; q++) acc[mf][nf][q] = 0.f;

    auto load_stage = [&](int s) {
        const int buf = s % 3;
        const uint32_t ab = sb + buf * STAGE_BYTES;
        const uint32_t bb = ab + 16384;
        const int k0 = s * 64;
#pragma unroll
        for (int i = 0; i < 8; i++) {
            int o = tid + i * 256;
            int oo = o & 1023;
            int row = oo >> 3, c = oo & 7;
            uint32_t off = sw128((uint32_t)(row * 128 + c * 16));
            if (o < 1024) {
                int sr = m0 + row; if (sr > M - 1) sr = M - 1;
                cp16(ab + off, A + (long long)sr * 512 + k0 + c * 8);
            } else {
                cp16(bb + off, W + (long long)(n0 + row) * 512 + k0 + c * 8);
            }
        }
    };

    load_stage(0); cp_commit();
    load_stage(1); cp_commit();

    const int a_row = (lane & 15);
    const int a_c16 = (lane >> 4);
    const int b_row = ((lane >> 4) << 3) + (lane & 7);
    const int b_c16 = ((lane >> 3) & 1);

    for (int s = 0; s < 8; s++) {
        cp_wait1();
        __syncthreads();
        const int buf = s % 3;
        const uint32_t ab = sb + buf * STAGE_BYTES;
        const uint32_t bb = ab + 16384;

#pragma unroll
        for (int ks = 0; ks < 4; ks++) {
            uint32_t af[4][4], bf[2][4];
#pragma unroll
            for (int mf = 0; mf < 4; mf++) {
                int m = wm * 64 + mf * 16 + a_row;
                ldm_x4(af[mf], ab + sw128((uint32_t)(m * 128 + ks * 32 + a_c16 * 16)));
            }
#pragma unroll
            for (int np = 0; np < 2; np++) {
                int n = wn * 32 + np * 16 + b_row;
                ldm_x4(bf[np], bb + sw128((uint32_t)(n * 128 + ks * 32 + b_c16 * 16)));
            }
#pragma unroll
            for (int mf = 0; mf < 4; mf++) {
                mma_fp16(acc[mf][0], af[mf][0], af[mf][1], af[mf][2], af[mf][3],
                         bf[0][0], bf[0][1]);
                mma_fp16(acc[mf][1], af[mf][0], af[mf][1], af[mf][2], af[mf][3],
                         bf[0][2], bf[0][3]);
                mma_fp16(acc[mf][2], af[mf][0], af[mf][1], af[mf][2], af[mf][3],
                         bf[1][0], bf[1][1]);
                mma_fp16(acc[mf][3], af[mf][0], af[mf][1], af[mf][2], af[mf][3],
                         bf[1][2], bf[1][3]);
            }
        }
        if (s + 2 < 8) load_stage(s + 2);
        cp_commit();
    }

#pragma unroll
    for (int mf = 0; mf < 4; mf++) {
#pragma unroll
        for (int h = 0; h < 2; h++) {
            int m = m0 + wm * 64 + mf * 16 + g + h * 8;
            if (m >= M) continue;
            long long orow;
            if (mode == 2) {
                int b_ = m / 3150, tq = (m / 50) % 63, i_ = m % 50;
                orow = ((long long)(b_ * 64 + tq + 1) * 50 + i_) * 512;
            } else {
                orow = (long long)m * 512;
            }
            long long arow = (long long)m * 512;
#pragma unroll
            for (int nf = 0; nf < 4; nf++) {
                int n = n0 + wn * 32 + nf * 8 + t * 2;
                float v0 = acc[mf][nf][h * 2 + 0];
                float v1 = acc[mf][nf][h * 2 + 1];
                float o0, o1;
                if (mode == 0) {
                    o0 = v0 + bias[n]; o1 = v1 + bias[n + 1];
                } else if (mode == 1) {
                    o0 = fmaxf(v0 + bias[n], 0.f);
                    o1 = fmaxf(v1 + bias[n + 1], 0.f);
                } else if (mode == 2) {
                    o0 = add2[orow + n]     + add1[arow + n]     + fmaxf(v0 + bias[n], 0.f);
                    o1 = add2[orow + n + 1] + add1[arow + n + 1] + fmaxf(v1 + bias[n + 1], 0.f);
                } else {
                    o0 = add1[arow + n]     + fmaxf(v0, 0.f);
                    o1 = add1[arow + n + 1] + fmaxf(v1, 0.f);
                }
                *(float2*)(C + orow + n) = make_float2(o0, o1);
                if (Ch)
                    *(__half2*)(Ch + orow + n) = __floats2half2_rn(o0, o1);
            }
        }
    }
}

// ---------------------------------------------------------------------------
// Sparse fused attention, 512 threads, fp16 node storage (fp32 accumulate).
// ---------------------------------------------------------------------------
#define ATTN_SMEM_BYTES (50*512*2 + 3*512*2 + 50*52*4 + 8*52*4 + 64)

__global__ __launch_bounds__(512) void attn_kernel(
    const __half* __restrict__ x, const float* __restrict__ edge,
    const float* __restrict__ lng, const float* __restrict__ lnb,
    float* __restrict__ spatial, float* __restrict__ attn_out)
{
    extern __shared__ char smraw[];
    __half2* xs = (__half2*)smraw;                       // [50][256]
    __half2* es = xs + 50 * 256;                         // [3][256]
    float*   S  = (float*)(es + 3 * 256);                // [50][52]
    float*   rq  = S + 50 * 52;
    float*   rk0 = rq + 52;
    float*   rk1 = rk0 + 52;
    float*   d0  = rk1 + 52;
    float*   d1  = d0 + 52;
    float*   d2  = d1 + 52;
    float*   sc  = d2 + 52;

    const int bt = blockIdx.x;
    const int tid = threadIdx.x;
    const int wid = tid >> 5, lane = tid & 31;
    const __half* xg = x + (long long)bt * 50 * 512;

    for (int idx = tid; idx < 3200; idx += 512)
        ((uint4*)xs)[idx] = ((const uint4*)xg)[idx];
    for (int idx = tid; idx < 768; idx += 512) {
        float2 v = ((const float2*)edge)[idx];
        es[idx] = __floats2half2_rn(v.x, v.y);
    }
    __syncthreads();

    // ---- window dots
    for (int i = wid; i < 49; i += 16) {
        float2 ai[8];
        ldcvt16(ai, xs + i * 256, lane);
        int qr = i / 7, qc = i - qr * 7;
        int r0 = qr - 1; if (r0 < 0) r0 = 0;
        int c0 = qc - 1; if (c0 < 0) c0 = 0; if (c0 > 4) c0 = 4;
        float part[9];
#pragma unroll
        for (int a = 0; a < 3; a++) {
            int kr = r0 + a;
            int krc = kr > 6 ? 6 : kr;
#pragma unroll
            for (int b = 0; b < 3; b++)
                part[a * 3 + b] = dot16h(ai, xs + (krc * 7 + c0 + b) * 256, lane);
        }
#pragma unroll
        for (int q = 0; q < 9; q++) part[q] = wreduce(part[q]);
        if (lane == 0) {
#pragma unroll
            for (int a = 0; a < 3; a++) {
                int kr = r0 + a;
                if (kr <= 6) {
#pragma unroll
                    for (int b = 0; b < 3; b++)
                        S[i * 52 + kr * 7 + c0 + b] = part[a * 3 + b];
                }
            }
        }
    }

    // ---- row/col 49 dots
    {
        float2 a49[8];
        ldcvt16(a49, xs + 49 * 256, lane);
        float part[4];
#pragma unroll
        for (int q = 0; q < 4; q++) {
            int j = wid + q * 16;
            int jc = j < 50 ? j : 49;
            part[q] = dot16h(a49, xs + jc * 256, lane);
        }
#pragma unroll
        for (int q = 0; q < 4; q++) part[q] = wreduce(part[q]);
        if (lane == 0) {
#pragma unroll
            for (int q = 0; q < 4; q++) {
                int j = wid + q * 16;
                if (j < 50) { S[49 * 52 + j] = part[q]; S[j * 52 + 49] = part[q]; }
            }
        }
    }

    // ---- edge dots d_k[i] and E_k
#pragma unroll
    for (int q = 0; q < 4; q++) {
        int i = wid + q * 16;
        if (i < 50) {
            float2 ai[8];
            ldcvt16(ai, xs + i * 256, lane);
            float p0 = dot16h(ai, es, lane);
            float p1 = dot16h(ai, es + 256, lane);
            float p2 = dot16h(ai, es + 512, lane);
            p0 = wreduce(p0); p1 = wreduce(p1); p2 = wreduce(p2);
            if (lane == 0) { d0[i] = p0; d1[i] = p1; d2[i] = p2; }
        }
    }
    if (wid < 3) {
        float2 ek[8];
        ldcvt16(ek, es + wid * 256, lane);
        float v = wreduce(dot16h(ek, es + wid * 256, lane));
        if (lane == 0) sc[wid] = v;
    }
    __syncthreads();

    // ---- norms
    if (tid < 50) {
        float gd = S[tid * 53];
        rq[tid]  = 1.f / fmaxf(sqrtf(gd), 1e-12f);
        rk0[tid] = 1.f / fmaxf(sqrtf(gd + 2.f * d0[tid] + sc[0]), 1e-12f);
        rk1[tid] = 1.f / fmaxf(sqrtf(gd + 2.f * d1[tid] + sc[1]), 1e-12f);
    } else if (tid == 50) {
        sc[3] = 1.f / fmaxf(sqrtf(S[49 * 53] + 2.f * d2[49] + sc[2]), 1e-12f);
    }
    __syncthreads();

    const float rk2  = sc[3];
    const float d149 = d1[49];
    const float rq49 = rq[49];

    // ---- scores (dense, in place)
    for (int p = tid; p < 2500; p += 512) {
        int i = p / 50, j = p - i * 50;
        float v;
        if (i == j)        v = NEGBIG;
        else if (j == 49)  v = (S[i * 52 + 49] + d2[i]) * rq[i] * rk2;
        else if (i == 49)  v = (S[49 * 52 + j] + d149) * rq49 * rk1[j];
        else {
            int qr = i / 7, qc = i - qr * 7;
            int kr = j / 7, kc = j - kr * 7;
            int r0 = qr - 1; if (r0 < 0) r0 = 0;
            int c0 = qc - 1; if (c0 < 0) c0 = 0; if (c0 > 4) c0 = 4;
            bool ok = (kr >= r0) && (kr <= r0 + 2) && (kc >= c0) && (kc <= c0 + 2);
            v = ok ? (S[i * 52 + j] + d0[i]) * rq[i] * rk0[j] : NEGBIG;
        }
        S[i * 52 + j] = v;
    }
    __syncthreads();

    // ---- softmax: warp per row
    for (int i = wid; i < 50; i += 16) {
        float* row = S + i * 52;
        float v0 = (lane < 50)      ? row[lane]      : -3.4e38f;
        float v1 = (lane + 32 < 50) ? row[lane + 32] : -3.4e38f;
        float mx = fmaxf(v0, v1);
#pragma unroll
        for (int o = 16; o; o >>= 1) mx = fmaxf(mx, __shfl_xor_sync(0xffffffffu, mx, o));
        float e0 = (lane < 50)      ? expf(v0 - mx) : 0.f;
        float e1 = (lane + 32 < 50) ? expf(v1 - mx) : 0.f;
        float s = wreduce(e0 + e1);
        float inv = 1.f / s;
        if (lane < 50)      row[lane]      = e0 * inv;
        if (lane + 32 < 50) row[lane + 32] = e1 * inv;
    }
    __syncthreads();

    // ---- write attention (last layer only)
    if (attn_out) {
        for (int p = tid; p < 2500; p += 512)
            attn_out[(long long)bt * 2500 + p] = S[(p / 50) * 52 + (p % 50)];
    }

    // ---- sparse aggregation + residual + LN + relu
    for (int i = wid; i < 50; i += 16) {
        float2 acc[8];
#pragma unroll
        for (int q = 0; q < 8; q++) acc[q] = make_float2(0.f, 0.f);
        const float aL = S[i * 52 + 49];

        auto addj = [&](int j, float w) {
            const uint4* r4 = (const uint4*)(xs + j * 256);
            uint4 u0 = r4[lane];
            uint4 u1 = r4[lane + 32];
            const __half2* h0 = (const __half2*)&u0;
            const __half2* h1 = (const __half2*)&u1;
#pragma unroll
            for (int q = 0; q < 4; q++) {
                float2 v0 = __half22float2(h0[q]);
                float2 v1 = __half22float2(h1[q]);
                acc[q].x += w * v0.x;     acc[q].y += w * v0.y;
                acc[4 + q].x += w * v1.x; acc[4 + q].y += w * v1.y;
            }
        };

        if (i < 49) {
            int qr = i / 7, qc = i - qr * 7;
            int r0 = qr - 1; if (r0 < 0) r0 = 0;
            int c0 = qc - 1; if (c0 < 0) c0 = 0; if (c0 > 4) c0 = 4;
            for (int a = 0; a < 3; a++) {
                int kr = r0 + a;
                if (kr > 6) break;
                for (int b = 0; b < 3; b++) {
                    int j = kr * 7 + c0 + b;
                    addj(j, S[i * 52 + j]);
                }
            }
            addj(49, aL);
        } else {
            for (int j = 0; j < 49; j++) addj(j, S[49 * 52 + j]);
        }

        // y = acc + (1-aL)*esel + aL*e2 + x_i
        float2 ese[8], e2v[8], xi[8];
        ldcvt16(ese, es + (i < 49 ? 0 : 256), lane);
        ldcvt16(e2v, es + 512, lane);
        ldcvt16(xi, xs + i * 256, lane);
        const float w1 = 1.f - aL;
        float2 y[8];
        float s1 = 0.f;
#pragma unroll
        for (int q = 0; q < 8; q++) {
            y[q].x = acc[q].x + w1 * ese[q].x + aL * e2v[q].x + xi[q].x;
            y[q].y = acc[q].y + w1 * ese[q].y + aL * e2v[q].y + xi[q].y;
            s1 += y[q].x + y[q].y;
        }
        s1 = wreduce(s1);
        float mean = s1 * (1.f / 512.f);
        float s2 = 0.f;
#pragma unroll
        for (int q = 0; q < 8; q++) {
            float dx = y[q].x - mean, dy = y[q].y - mean;
            s2 += dx * dx + dy * dy;
        }
        s2 = wreduce(s2);
        float inv = rsqrtf(s2 * (1.f / 512.f) + 1e-5f);

        // lane owns elements [lane*8, lane*8+8) and [256+lane*8, 256+lane*8+8)
        const float4* gp = (const float4*)lng;
        const float4* bp = (const float4*)lnb;
        float4* op = (float4*)(spatial + ((long long)bt * 50 + i) * 512);
#pragma unroll
        for (int half = 0; half < 2; half++) {
#pragma unroll
            for (int q = 0; q < 2; q++) {
                int c = half * 64 + lane * 2 + q;         // float4 index
                float2 ya = y[half * 4 + q * 2];
                float2 yb = y[half * 4 + q * 2 + 1];
                float4 gv = gp[c], bv = bp[c], o;
                o.x = fmaxf((ya.x - mean) * inv * gv.x + bv.x, 0.f);
                o.y = fmaxf((ya.y - mean) * inv * gv.y + bv.y, 0.f);
                o.z = fmaxf((yb.x - mean) * inv * gv.z + bv.z, 0.f);
                o.w = fmaxf((yb.y - mean) * inv * gv.w + bv.w, 0.f);
                op[c] = o;
            }
        }
    }
}

// ---------------------------------------------------------------------------
// LayerNorm (warp per 512-row); optional t=0 source override; half out.
// ---------------------------------------------------------------------------
__global__ __launch_bounds__(256) void ln_kernel(
    const float* __restrict__ in, const float* __restrict__ in0,
    float* __restrict__ outf, __half* __restrict__ outh,
    const float* __restrict__ g, const float* __restrict__ b,
    int rows, int do_relu)
{
    int warp = (blockIdx.x * 256 + threadIdx.x) >> 5;
    int lane = threadIdx.x & 31;
    if (warp >= rows) return;
    const float* src = in;
    if (in0) {
        int t = (warp / 50) & 63;
        if (t == 0) src = in0;
    }
    const float4* ip = (const float4*)(src + (long long)warp * 512);
    float4 v[4];
    float s = 0.f;
#pragma unroll
    for (int q = 0; q < 4; q++) {
        v[q] = ip[lane + 32 * q];
        s += v[q].x + v[q].y + v[q].z + v[q].w;
    }
#pragma unroll
    for (int off = 16; off; off >>= 1) s += __shfl_xor_sync(0xffffffffu, s, off);
    float mean = s * (1.f / 512.f);
    float ss = 0.f;
#pragma unroll
    for (int q = 0; q < 4; q++) {
        float dx = v[q].x - mean, dy = v[q].y - mean, dz = v[q].z - mean, dw = v[q].w - mean;
        ss += dx * dx + dy * dy + dz * dz + dw * dw;
    }
#pragma unroll
    for (int off = 16; off; off >>= 1) ss += __shfl_xor_sync(0xffffffffu, ss, off);
    float inv = rsqrtf(ss * (1.f / 512.f) + 1e-5f);
    const float4* gp = (const float4*)g;
    const float4* bp = (const float4*)b;
#pragma unroll
    for (int q = 0; q < 4; q++) {
        int c = lane + 32 * q;
        float4 gv = gp[c], bv = bp[c], o;
        o.x = (v[q].x - mean) * inv * gv.x + bv.x;
        o.y = (v[q].y - mean) * inv * gv.y + bv.y;
        o.z = (v[q].z - mean) * inv * gv.z + bv.z;
        o.w = (v[q].w - mean) * inv * gv.w + bv.w;
        if (do_relu) {
            o.x = fmaxf(o.x, 0.f); o.y = fmaxf(o.y, 0.f);
            o.z = fmaxf(o.z, 0.f); o.w = fmaxf(o.w, 0.f);
        }
        if (outf) ((float4*)(outf + (long long)warp * 512))[c] = o;
        if (outh) {
            __half2* hp = (__half2*)(outh + (long long)warp * 512);
            hp[c * 2 + 0] = __floats2half2_rn(o.x, o.y);
            hp[c * 2 + 1] = __floats2half2_rn(o.z, o.w);
        }
    }
}

// ---------------------------------------------------------------------------
// cos similarity + half GEMM inputs: hc = cos*prev, hs = (1-cos)*cur
// ---------------------------------------------------------------------------
__global__ __launch_bounds__(256) void cos_kernel(
    const float* __restrict__ spatial, float* __restrict__ cosv,
    __half* __restrict__ hc, __half* __restrict__ hs)
{
    int warp = (blockIdx.x * 256 + threadIdx.x) >> 5;
    int lane = threadIdx.x & 31;
    if (warp >= 50400) return;
    int i = warp % 50;
    int tq = (warp / 50) % 63;
    int b_ = warp / 3150;
    long long cur_off  = (((long long)b_ * 64 + tq + 1) * 50 + i) * 512;
    long long prev_off = (((long long)b_ * 64 + tq) * 50 + i) * 512;
    const float4* cp = (const float4*)(spatial + cur_off);
    const float4* pp = (const float4*)(spatial + prev_off);
    float4 cb[4], pb[4];
    float dt = 0.f, na = 0.f, nb = 0.f;
#pragma unroll
    for (int q = 0; q < 4; q++) {
        cb[q] = cp[lane + 32 * q];
        pb[q] = pp[lane + 32 * q];
        dt += cb[q].x * pb[q].x + cb[q].y * pb[q].y + cb[q].z * pb[q].z + cb[q].w * pb[q].w;
        na += cb[q].x * cb[q].x + cb[q].y * cb[q].y + cb[q].z * cb[q].z + cb[q].w * cb[q].w;
        nb += pb[q].x * pb[q].x + pb[q].y * pb[q].y + pb[q].z * pb[q].z + pb[q].w * pb[q].w;
    }
#pragma unroll
    for (int off = 16; off; off >>= 1) {
        dt += __shfl_xor_sync(0xffffffffu, dt, off);
        na += __shfl_xor_sync(0xffffffffu, na, off);
        nb += __shfl_xor_sync(0xffffffffu, nb, off);
    }
    float cv = dt / (fmaxf(sqrtf(na), 1e-8f) * fmaxf(sqrtf(nb), 1e-8f));
    if (lane == 0) cosv[warp] = cv;
    __half2* hcp = (__half2*)(hc + (long long)warp * 512);
    __half2* hsp = (__half2*)(hs + (long long)warp * 512);
    float w1 = 1.f - cv;
#pragma unroll
    for (int q = 0; q < 4; q++) {
        int c = lane + 32 * q;
        hcp[c * 2 + 0] = __floats2half2_rn(cv * pb[q].x, cv * pb[q].y);
        hcp[c * 2 + 1] = __floats2half2_rn(cv * pb[q].z, cv * pb[q].w);
        hsp[c * 2 + 0] = __floats2half2_rn(w1 * cb[q].x, w1 * cb[q].y);
        hsp[c * 2 + 1] = __floats2half2_rn(w1 * cb[q].z, w1 * cb[q].w);
    }
}

// ---------------------------------------------------------------------------
// Host launcher
// ---------------------------------------------------------------------------
extern "C" void kernel_launch(void* const* d_in, const int* in_sizes, int n_in,
                              void* d_out, int out_size)
{
    const float* visual = (const float*)d_in[0];
    const float* audio  = (const float*)d_in[1];
    const float* in_W   = (const float*)d_in[2];
    const float* in_b   = (const float*)d_in[3];
    const float* out_W  = (const float*)d_in[4];
    const float* out_b  = (const float*)d_in[5];

    float *node, *spatial, *t1, *t2, *attnb, *cosb;
    __half *hA, *hc, *hs, *ht3, *hnode, *wh;
    cudaGetSymbolAddress((void**)&node,    g_node);
    cudaGetSymbolAddress((void**)&spatial, g_spatial);
    cudaGetSymbolAddress((void**)&t1,      g_t1);
    cudaGetSymbolAddress((void**)&t2,      g_t2);
    cudaGetSymbolAddress((void**)&attnb,   g_attn);
    cudaGetSymbolAddress((void**)&cosb,    g_cos);
    cudaGetSymbolAddress((void**)&hA,      g_hA);
    cudaGetSymbolAddress((void**)&hc,      g_hc);
    cudaGetSymbolAddress((void**)&hs,      g_hs);
    cudaGetSymbolAddress((void**)&ht3,     g_ht3);
    cudaGetSymbolAddress((void**)&hnode,   g_hnode);
    cudaGetSymbolAddress((void**)&wh,      g_wh);

    cudaFuncSetAttribute(attn_kernel,
                         cudaFuncAttributeMaxDynamicSharedMemorySize, ATTN_SMEM_BYTES);
    cudaFuncSetAttribute(gemm_fp16,
                         cudaFuncAttributeMaxDynamicSharedMemorySize, GEMM_SMEM);

    wround8_kernel<<<2048, 256>>>(
        in_W, (const float*)d_in[9], (const float*)d_in[11], (const float*)d_in[13],
        (const float*)d_in[17], (const float*)d_in[19], (const float*)d_in[21], out_W,
        wh);

    concat_kernel<<<25600, 256>>>(visual, audio, hA);
    dim3 gAll(4, 400);
    dim3 gTmp(4, 394);
    gemm_fp16<<<gAll, 256, GEMM_SMEM>>>(hA, wh + 0 * 262144, in_b,
                                        nullptr, nullptr, node, hnode,
                                        51200, 0);

    for (int L = 0; L < 2; L++) {
        int base = 6 + L * 8;
        const float* edge = (const float*)d_in[base + 0];
        const float* lng  = (const float*)d_in[base + 1];
        const float* lnb  = (const float*)d_in[base + 2];
        const float* bc   = (const float*)d_in[base + 4];
        const float* bs   = (const float*)d_in[base + 6];
        const __half* wc  = wh + (long long)(1 + L * 3) * 262144;
        const __half* ws  = wh + (long long)(2 + L * 3) * 262144;
        const __half* wo  = wh + (long long)(3 + L * 3) * 262144;

        attn_kernel<<<1024, 512, ATTN_SMEM_BYTES>>>(
            hnode, edge, lng, lnb, spatial, (L == 1) ? attnb : nullptr);
        cos_kernel<<<6300, 256>>>(spatial, cosb, hc, hs);
        gemm_fp16<<<gTmp, 256, GEMM_SMEM>>>(hc, wc, bc, nullptr, nullptr,
                                            t1, nullptr, 50400, 1);
        gemm_fp16<<<gTmp, 256, GEMM_SMEM>>>(hs, ws, bs, t1, spatial,
                                            t2, nullptr, 50400, 2);
        ln_kernel<<<6400, 256>>>(t2, spatial, nullptr, ht3, lng, lnb, 51200, 0);
        gemm_fp16<<<gAll, 256, GEMM_SMEM>>>(ht3, wo, nullptr, node, nullptr,
                                            node, hnode, 51200, 3);
    }

    gemm_fp16<<<gAll, 256, GEMM_SMEM>>>(hnode, wh + 7LL * 262144, out_b,
                                        nullptr, nullptr, (float*)d_out,
                                        nullptr, 51200, 0);

    long long need = OUT_ELEMS + ATTN_ELEMS + COS_ELEMS;
    if ((long long)out_size >= need) {
        cudaMemcpyAsync((float*)d_out + OUT_ELEMS, attnb,
                        ATTN_ELEMS * sizeof(float), cudaMemcpyDeviceToDevice);
        cudaMemcpyAsync((float*)d_out + OUT_ELEMS + ATTN_ELEMS, cosb,
                        COS_ELEMS * sizeof(float), cudaMemcpyDeviceToDevice);
    }
}

// round 14
// speedup vs baseline: 1.9878x; 1.0748x over previous
#include <cuda_runtime.h>
#include <cuda_fp16.h>
#include <cstdint>

// ---------------------------------------------------------------------------
// Problem: B=16, T=64, N=49(+1)=50 nodes, D=H=512, WIN=7
// ---------------------------------------------------------------------------
#define NEGBIG (-1e9f)

static const long long OUT_ELEMS  = 51200LL * 512;
static const long long ATTN_ELEMS = 1024LL * 2500;
static const long long COS_ELEMS  = 50400LL;

// ---------------------------------------------------------------------------
// Device scratch
// ---------------------------------------------------------------------------
__device__ float  g_node[51200 * 512];
__device__ float  g_spatial[51200 * 512];
__device__ float  g_t1[51200 * 512];
__device__ float  g_t2[51200 * 512];
__device__ float  g_attn[1024 * 2500];
__device__ float  g_cos[50400];
__device__ __half g_hA[51200 * 512];
__device__ __half g_hc[50400 * 512];
__device__ __half g_hs[50400 * 512];
__device__ __half g_ht3[51200 * 512];
__device__ __half g_hnode[51200 * 512];
__device__ __half g_wh[8 * 512 * 512];

// ---------------------------------------------------------------------------
// helpers
// ---------------------------------------------------------------------------
__device__ __forceinline__ uint32_t smem_u32(const void* p) {
    uint32_t a;
    asm("{ .reg .u64 t; cvta.to.shared.u64 t, %1; cvt.u32.u64 %0, t; }"
        : "=r"(a) : "l"(p));
    return a;
}
__device__ __forceinline__ uint32_t sw128(uint32_t off) {
    return off ^ ((off >> 3) & 0x70);
}
__device__ __forceinline__ void cp16(uint32_t dst, const void* src) {
    asm volatile("cp.async.cg.shared.global [%0], [%1], 16;\n"
                 :: "r"(dst), "l"(src));
}
__device__ __forceinline__ void cp_commit() {
    asm volatile("cp.async.commit_group;\n" ::: "memory");
}
__device__ __forceinline__ void cp_wait1() {
    asm volatile("cp.async.wait_group 1;\n" ::: "memory");
}
__device__ __forceinline__ void ldm_x4(uint32_t r[4], uint32_t addr) {
    asm volatile("ldmatrix.sync.aligned.m8n8.x4.shared.b16 {%0,%1,%2,%3}, [%4];"
                 : "=r"(r[0]), "=r"(r[1]), "=r"(r[2]), "=r"(r[3]) : "r"(addr));
}
__device__ __forceinline__ void mma_fp16(
    float c[4], uint32_t a0, uint32_t a1, uint32_t a2, uint32_t a3,
    uint32_t b0, uint32_t b1)
{
    asm volatile(
        "mma.sync.aligned.m16n8k16.row.col.f32.f16.f16.f32 "
        "{%0,%1,%2,%3}, {%4,%5,%6,%7}, {%8,%9}, {%0,%1,%2,%3};\n"
        : "+f"(c[0]), "+f"(c[1]), "+f"(c[2]), "+f"(c[3])
        : "r"(a0), "r"(a1), "r"(a2), "r"(a3), "r"(b0), "r"(b1));
}
__device__ __forceinline__ float wreduce(float s) {
#pragma unroll
    for (int o = 16; o; o >>= 1) s += __shfl_xor_sync(0xffffffffu, s, o);
    return s;
}
// lane owns 16 halves of a 512-elem row: uint4 [lane] and [lane+32].
__device__ __forceinline__ void ldcvt16(float2 a[8], const __half2* row, int lane) {
    const uint4* r4 = (const uint4*)row;
    uint4 u0 = r4[lane];
    uint4 u1 = r4[lane + 32];
    const __half2* h0 = (const __half2*)&u0;
    const __half2* h1 = (const __half2*)&u1;
#pragma unroll
    for (int k = 0; k < 4; k++) {
        a[k]     = __half22float2(h0[k]);
        a[4 + k] = __half22float2(h1[k]);
    }
}
__device__ __forceinline__ float dot16h(const float2 a[8], const __half2* row, int lane) {
    const uint4* r4 = (const uint4*)row;
    uint4 u0 = r4[lane];
    uint4 u1 = r4[lane + 32];
    const __half2* h0 = (const __half2*)&u0;
    const __half2* h1 = (const __half2*)&u1;
    float s = 0.f;
#pragma unroll
    for (int k = 0; k < 4; k++) {
        float2 b0 = __half22float2(h0[k]);
        float2 b1 = __half22float2(h1[k]);
        s += a[k].x * b0.x + a[k].y * b0.y;
        s += a[4 + k].x * b1.x + a[4 + k].y * b1.y;
    }
    return s;
}

// ---------------------------------------------------------------------------
// all 8 weights -> half in one launch (grid 2048)
// ---------------------------------------------------------------------------
__global__ __launch_bounds__(256) void wround8_kernel(
    const float* s0, const float* s1, const float* s2, const float* s3,
    const float* s4, const float* s5, const float* s6, const float* s7,
    __half* __restrict__ dst)
{
    int w = blockIdx.x >> 8;
    const float* s =
        (w == 0) ? s0 : (w == 1) ? s1 : (w == 2) ? s2 : (w == 3) ? s3 :
        (w == 4) ? s4 : (w == 5) ? s5 : (w == 6) ? s6 : s7;
    __half2* d = (__half2*)(dst + (long long)w * 262144);
    int i = (blockIdx.x & 255) * 256 + threadIdx.x;
    float4 v = ((const float4*)s)[i];
    d[i * 2 + 0] = __floats2half2_rn(v.x, v.y);
    d[i * 2 + 1] = __floats2half2_rn(v.z, v.w);
}

// ---------------------------------------------------------------------------
// concat(visual, audio) -> half [51200, 512]
// ---------------------------------------------------------------------------
__global__ __launch_bounds__(256) void concat_kernel(
    const float* __restrict__ vis, const float* __restrict__ aud,
    __half* __restrict__ out)
{
    long long idx = (long long)blockIdx.x * 256 + threadIdx.x;
    if (idx >= (long long)51200 * 128) return;
    long long r = idx >> 7;
    int hv = (int)(idx & 127);
    int bt = (int)(r / 50), i = (int)(r % 50);
    float4 v;
    if (i < 49)
        v = ((const float4*)vis)[((long long)bt * 49 + i) * 128 + hv];
    else
        v = ((const float4*)aud)[(long long)bt * 128 + hv];
    __half2* d = (__half2*)out;
    d[idx * 2 + 0] = __floats2half2_rn(v.x, v.y);
    d[idx * 2 + 1] = __floats2half2_rn(v.z, v.w);
}

// ---------------------------------------------------------------------------
// fp16 tensor-core NT GEMM: CTA 128x128, k-tile 64, 3-stage cp.async,
// 256 threads / 8 warps. C (fp32) and Ch (fp16) outputs both nullable.
// ---------------------------------------------------------------------------
#define STAGE_BYTES 32768
#define GEMM_SMEM   (3 * STAGE_BYTES)

__global__ __launch_bounds__(256) void gemm_fp16(
    const __half* __restrict__ A, const __half* __restrict__ W,
    const float* __restrict__ bias, const float* __restrict__ add1,
    const float* __restrict__ add2, float* __restrict__ C,
    __half* __restrict__ Ch, int M, int mode)
{
    extern __shared__ char smem[];
    const uint32_t sb = smem_u32(smem);

    const int tid = threadIdx.x;
    const int wid = tid >> 5, lane = tid & 31;
    const int wm = wid >> 2, wn = wid & 3;
    const int g = lane >> 2, t = lane & 3;
    const int m0 = blockIdx.y * 128;
    const int n0 = blockIdx.x * 128;

    float acc[4][4][4];
#pragma unroll
    for (int mf = 0; mf < 4; mf++)
#pragma unroll
        for (int nf = 0; nf < 4; nf++)
#pragma unroll
            for (int q = 0; q < 4; q++) acc[mf][nf][q] = 0.f;

    auto load_stage = [&](int s) {
        const int buf = s % 3;
        const uint32_t ab = sb + buf * STAGE_BYTES;
        const uint32_t bb = ab + 16384;
        const int k0 = s * 64;
#pragma unroll
        for (int i = 0; i < 8; i++) {
            int o = tid + i * 256;
            int oo = o & 1023;
            int row = oo >> 3, c = oo & 7;
            uint32_t off = sw128((uint32_t)(row * 128 + c * 16));
            if (o < 1024) {
                int sr = m0 + row; if (sr > M - 1) sr = M - 1;
                cp16(ab + off, A + (long long)sr * 512 + k0 + c * 8);
            } else {
                cp16(bb + off, W + (long long)(n0 + row) * 512 + k0 + c * 8);
            }
        }
    };

    load_stage(0); cp_commit();
    load_stage(1); cp_commit();

    const int a_row = (lane & 15);
    const int a_c16 = (lane >> 4);
    const int b_row = ((lane >> 4) << 3) + (lane & 7);
    const int b_c16 = ((lane >> 3) & 1);

    for (int s = 0; s < 8; s++) {
        cp_wait1();
        __syncthreads();
        const int buf = s % 3;
        const uint32_t ab = sb + buf * STAGE_BYTES;
        const uint32_t bb = ab + 16384;

#pragma unroll
        for (int ks = 0; ks < 4; ks++) {
            uint32_t af[4][4], bf[2][4];
#pragma unroll
            for (int mf = 0; mf < 4; mf++) {
                int m = wm * 64 + mf * 16 + a_row;
                ldm_x4(af[mf], ab + sw128((uint32_t)(m * 128 + ks * 32 + a_c16 * 16)));
            }
#pragma unroll
            for (int np = 0; np < 2; np++) {
                int n = wn * 32 + np * 16 + b_row;
                ldm_x4(bf[np], bb + sw128((uint32_t)(n * 128 + ks * 32 + b_c16 * 16)));
            }
#pragma unroll
            for (int mf = 0; mf < 4; mf++) {
                mma_fp16(acc[mf][0], af[mf][0], af[mf][1], af[mf][2], af[mf][3],
                         bf[0][0], bf[0][1]);
                mma_fp16(acc[mf][1], af[mf][0], af[mf][1], af[mf][2], af[mf][3],
                         bf[0][2], bf[0][3]);
                mma_fp16(acc[mf][2], af[mf][0], af[mf][1], af[mf][2], af[mf][3],
                         bf[1][0], bf[1][1]);
                mma_fp16(acc[mf][3], af[mf][0], af[mf][1], af[mf][2], af[mf][3],
                         bf[1][2], bf[1][3]);
            }
        }
        if (s + 2 < 8) load_stage(s + 2);
        cp_commit();
    }

#pragma unroll
    for (int mf = 0; mf < 4; mf++) {
#pragma unroll
        for (int h = 0; h < 2; h++) {
            int m = m0 + wm * 64 + mf * 16 + g + h * 8;
            if (m >= M) continue;
            long long orow;
            if (mode == 2) {
                int b_ = m / 3150, tq = (m / 50) % 63, i_ = m % 50;
                orow = ((long long)(b_ * 64 + tq + 1) * 50 + i_) * 512;
            } else {
                orow = (long long)m * 512;
            }
            long long arow = (long long)m * 512;
#pragma unroll
            for (int nf = 0; nf < 4; nf++) {
                int n = n0 + wn * 32 + nf * 8 + t * 2;
                float v0 = acc[mf][nf][h * 2 + 0];
                float v1 = acc[mf][nf][h * 2 + 1];
                float o0, o1;
                if (mode == 0) {
                    o0 = v0 + bias[n]; o1 = v1 + bias[n + 1];
                } else if (mode == 1) {
                    o0 = fmaxf(v0 + bias[n], 0.f);
                    o1 = fmaxf(v1 + bias[n + 1], 0.f);
                } else if (mode == 2) {
                    o0 = add2[orow + n]     + add1[arow + n]     + fmaxf(v0 + bias[n], 0.f);
                    o1 = add2[orow + n + 1] + add1[arow + n + 1] + fmaxf(v1 + bias[n + 1], 0.f);
                } else {
                    o0 = add1[arow + n]     + fmaxf(v0, 0.f);
                    o1 = add1[arow + n + 1] + fmaxf(v1, 0.f);
                }
                if (C)
                    *(float2*)(C + orow + n) = make_float2(o0, o1);
                if (Ch)
                    *(__half2*)(Ch + orow + n) = __floats2half2_rn(o0, o1);
            }
        }
    }
}

// ---------------------------------------------------------------------------
// Sparse fused attention, 256 threads (2 CTAs/SM), fp16 node storage.
// ---------------------------------------------------------------------------
#define ATTN_SMEM_BYTES (50*512*2 + 3*512*2 + 50*52*4 + 8*52*4 + 64)

__global__ __launch_bounds__(256) void attn_kernel(
    const __half* __restrict__ x, const float* __restrict__ edge,
    const float* __restrict__ lng, const float* __restrict__ lnb,
    float* __restrict__ spatial, float* __restrict__ attn_out)
{
    extern __shared__ char smraw[];
    __half2* xs = (__half2*)smraw;                       // [50][256]
    __half2* es = xs + 50 * 256;                         // [3][256]
    float*   S  = (float*)(es + 3 * 256);                // [50][52]
    float*   rq  = S + 50 * 52;
    float*   rk0 = rq + 52;
    float*   rk1 = rk0 + 52;
    float*   d0  = rk1 + 52;
    float*   d1  = d0 + 52;
    float*   d2  = d1 + 52;
    float*   sc  = d2 + 52;

    const int bt = blockIdx.x;
    const int tid = threadIdx.x;
    const int wid = tid >> 5, lane = tid & 31;
    const __half* xg = x + (long long)bt * 50 * 512;

    for (int idx = tid; idx < 3200; idx += 256)
        ((uint4*)xs)[idx] = ((const uint4*)xg)[idx];
    for (int idx = tid; idx < 768; idx += 256) {
        float2 v = ((const float2*)edge)[idx];
        es[idx] = __floats2half2_rn(v.x, v.y);
    }
    __syncthreads();

    // ---- window dots (warp per row, 8 warps)
    for (int i = wid; i < 49; i += 8) {
        float2 ai[8];
        ldcvt16(ai, xs + i * 256, lane);
        int qr = i / 7, qc = i - qr * 7;
        int r0 = qr - 1; if (r0 < 0) r0 = 0;
        int c0 = qc - 1; if (c0 < 0) c0 = 0; if (c0 > 4) c0 = 4;
        float part[9];
#pragma unroll
        for (int a = 0; a < 3; a++) {
            int kr = r0 + a;
            int krc = kr > 6 ? 6 : kr;
#pragma unroll
            for (int b = 0; b < 3; b++)
                part[a * 3 + b] = dot16h(ai, xs + (krc * 7 + c0 + b) * 256, lane);
        }
#pragma unroll
        for (int q = 0; q < 9; q++) part[q] = wreduce(part[q]);
        if (lane == 0) {
#pragma unroll
            for (int a = 0; a < 3; a++) {
                int kr = r0 + a;
                if (kr <= 6) {
#pragma unroll
                    for (int b = 0; b < 3; b++)
                        S[i * 52 + kr * 7 + c0 + b] = part[a * 3 + b];
                }
            }
        }
    }

    // ---- row/col 49 dots: 7 batched per warp (j = wid + q*8)
    {
        float2 a49[8];
        ldcvt16(a49, xs + 49 * 256, lane);
        float part[7];
#pragma unroll
        for (int q = 0; q < 7; q++) {
            int j = wid + q * 8;
            int jc = j < 50 ? j : 49;
            part[q] = dot16h(a49, xs + jc * 256, lane);
        }
#pragma unroll
        for (int q = 0; q < 7; q++) part[q] = wreduce(part[q]);
        if (lane == 0) {
#pragma unroll
            for (int q = 0; q < 7; q++) {
                int j = wid + q * 8;
                if (j < 50) { S[49 * 52 + j] = part[q]; S[j * 52 + 49] = part[q]; }
            }
        }
    }

    // ---- edge dots d_k[i] and E_k
    for (int i = wid; i < 50; i += 8) {
        float2 ai[8];
        ldcvt16(ai, xs + i * 256, lane);
        float p0 = dot16h(ai, es, lane);
        float p1 = dot16h(ai, es + 256, lane);
        float p2 = dot16h(ai, es + 512, lane);
        p0 = wreduce(p0); p1 = wreduce(p1); p2 = wreduce(p2);
        if (lane == 0) { d0[i] = p0; d1[i] = p1; d2[i] = p2; }
    }
    if (wid < 3) {
        float2 ek[8];
        ldcvt16(ek, es + wid * 256, lane);
        float v = wreduce(dot16h(ek, es + wid * 256, lane));
        if (lane == 0) sc[wid] = v;
    }
    __syncthreads();

    // ---- norms
    if (tid < 50) {
        float gd = S[tid * 53];
        rq[tid]  = 1.f / fmaxf(sqrtf(gd), 1e-12f);
        rk0[tid] = 1.f / fmaxf(sqrtf(gd + 2.f * d0[tid] + sc[0]), 1e-12f);
        rk1[tid] = 1.f / fmaxf(sqrtf(gd + 2.f * d1[tid] + sc[1]), 1e-12f);
    } else if (tid == 50) {
        sc[3] = 1.f / fmaxf(sqrtf(S[49 * 53] + 2.f * d2[49] + sc[2]), 1e-12f);
    }
    __syncthreads();

    const float rk2  = sc[3];
    const float d149 = d1[49];
    const float rq49 = rq[49];

    // ---- scores (dense, in place)
    for (int p = tid; p < 2500; p += 256) {
        int i = p / 50, j = p - i * 50;
        float v;
        if (i == j)        v = NEGBIG;
        else if (j == 49)  v = (S[i * 52 + 49] + d2[i]) * rq[i] * rk2;
        else if (i == 49)  v = (S[49 * 52 + j] + d149) * rq49 * rk1[j];
        else {
            int qr = i / 7, qc = i - qr * 7;
            int kr = j / 7, kc = j - kr * 7;
            int r0 = qr - 1; if (r0 < 0) r0 = 0;
            int c0 = qc - 1; if (c0 < 0) c0 = 0; if (c0 > 4) c0 = 4;
            bool ok = (kr >= r0) && (kr <= r0 + 2) && (kc >= c0) && (kc <= c0 + 2);
            v = ok ? (S[i * 52 + j] + d0[i]) * rq[i] * rk0[j] : NEGBIG;
        }
        S[i * 52 + j] = v;
    }
    __syncthreads();

    // ---- softmax: warp per row
    for (int i = wid; i < 50; i += 8) {
        float* row = S + i * 52;
        float v0 = (lane < 50)      ? row[lane]      : -3.4e38f;
        float v1 = (lane + 32 < 50) ? row[lane + 32] : -3.4e38f;
        float mx = fmaxf(v0, v1);
#pragma unroll
        for (int o = 16; o; o >>= 1) mx = fmaxf(mx, __shfl_xor_sync(0xffffffffu, mx, o));
        float e0 = (lane < 50)      ? expf(v0 - mx) : 0.f;
        float e1 = (lane + 32 < 50) ? expf(v1 - mx) : 0.f;
        float s = wreduce(e0 + e1);
        float inv = 1.f / s;
        if (lane < 50)      row[lane]      = e0 * inv;
        if (lane + 32 < 50) row[lane + 32] = e1 * inv;
    }
    __syncthreads();

    // ---- write attention (last layer only)
    if (attn_out) {
        for (int p = tid; p < 2500; p += 256)
            attn_out[(long long)bt * 2500 + p] = S[(p / 50) * 52 + (p % 50)];
    }

    // ---- sparse aggregation + residual + LN + relu
    for (int i = wid; i < 50; i += 8) {
        float2 acc[8];
#pragma unroll
        for (int q = 0; q < 8; q++) acc[q] = make_float2(0.f, 0.f);
        const float aL = S[i * 52 + 49];

        auto addj = [&](int j, float w) {
            const uint4* r4 = (const uint4*)(xs + j * 256);
            uint4 u0 = r4[lane];
            uint4 u1 = r4[lane + 32];
            const __half2* h0 = (const __half2*)&u0;
            const __half2* h1 = (const __half2*)&u1;
#pragma unroll
            for (int q = 0; q < 4; q++) {
                float2 v0 = __half22float2(h0[q]);
                float2 v1 = __half22float2(h1[q]);
                acc[q].x += w * v0.x;     acc[q].y += w * v0.y;
                acc[4 + q].x += w * v1.x; acc[4 + q].y += w * v1.y;
            }
        };

        if (i < 49) {
            int qr = i / 7, qc = i - qr * 7;
            int r0 = qr - 1; if (r0 < 0) r0 = 0;
            int c0 = qc - 1; if (c0 < 0) c0 = 0; if (c0 > 4) c0 = 4;
            for (int a = 0; a < 3; a++) {
                int kr = r0 + a;
                if (kr > 6) break;
                for (int b = 0; b < 3; b++) {
                    int j = kr * 7 + c0 + b;
                    addj(j, S[i * 52 + j]);
                }
            }
            addj(49, aL);
        } else {
            for (int j = 0; j < 49; j++) addj(j, S[49 * 52 + j]);
        }

        float2 ese[8], e2v[8], xi[8];
        ldcvt16(ese, es + (i < 49 ? 0 : 256), lane);
        ldcvt16(e2v, es + 512, lane);
        ldcvt16(xi, xs + i * 256, lane);
        const float w1 = 1.f - aL;
        float2 y[8];
        float s1 = 0.f;
#pragma unroll
        for (int q = 0; q < 8; q++) {
            y[q].x = acc[q].x + w1 * ese[q].x + aL * e2v[q].x + xi[q].x;
            y[q].y = acc[q].y + w1 * ese[q].y + aL * e2v[q].y + xi[q].y;
            s1 += y[q].x + y[q].y;
        }
        s1 = wreduce(s1);
        float mean = s1 * (1.f / 512.f);
        float s2 = 0.f;
#pragma unroll
        for (int q = 0; q < 8; q++) {
            float dx = y[q].x - mean, dy = y[q].y - mean;
            s2 += dx * dx + dy * dy;
        }
        s2 = wreduce(s2);
        float inv = rsqrtf(s2 * (1.f / 512.f) + 1e-5f);

        const float4* gp = (const float4*)lng;
        const float4* bp = (const float4*)lnb;
        float4* op = (float4*)(spatial + ((long long)bt * 50 + i) * 512);
#pragma unroll
        for (int half = 0; half < 2; half++) {
#pragma unroll
            for (int q = 0; q < 2; q++) {
                int c = half * 64 + lane * 2 + q;
                float2 ya = y[half * 4 + q * 2];
                float2 yb = y[half * 4 + q * 2 + 1];
                float4 gv = gp[c], bv = bp[c], o;
                o.x = fmaxf((ya.x - mean) * inv * gv.x + bv.x, 0.f);
                o.y = fmaxf((ya.y - mean) * inv * gv.y + bv.y, 0.f);
                o.z = fmaxf((yb.x - mean) * inv * gv.z + bv.z, 0.f);
                o.w = fmaxf((yb.y - mean) * inv * gv.w + bv.w, 0.f);
                op[c] = o;
            }
        }
    }
}

// ---------------------------------------------------------------------------
// LayerNorm (warp per 512-row); optional t=0 source override; half out.
// ---------------------------------------------------------------------------
__global__ __launch_bounds__(256) void ln_kernel(
    const float* __restrict__ in, const float* __restrict__ in0,
    float* __restrict__ outf, __half* __restrict__ outh,
    const float* __restrict__ g, const float* __restrict__ b,
    int rows, int do_relu)
{
    int warp = (blockIdx.x * 256 + threadIdx.x) >> 5;
    int lane = threadIdx.x & 31;
    if (warp >= rows) return;
    const float* src = in;
    if (in0) {
        int t = (warp / 50) & 63;
        if (t == 0) src = in0;
    }
    const float4* ip = (const float4*)(src + (long long)warp * 512);
    float4 v[4];
    float s = 0.f;
#pragma unroll
    for (int q = 0; q < 4; q++) {
        v[q] = ip[lane + 32 * q];
        s += v[q].x + v[q].y + v[q].z + v[q].w;
    }
#pragma unroll
    for (int off = 16; off; off >>= 1) s += __shfl_xor_sync(0xffffffffu, s, off);
    float mean = s * (1.f / 512.f);
    float ss = 0.f;
#pragma unroll
    for (int q = 0; q < 4; q++) {
        float dx = v[q].x - mean, dy = v[q].y - mean, dz = v[q].z - mean, dw = v[q].w - mean;
        ss += dx * dx + dy * dy + dz * dz + dw * dw;
    }
#pragma unroll
    for (int off = 16; off; off >>= 1) ss += __shfl_xor_sync(0xffffffffu, ss, off);
    float inv = rsqrtf(ss * (1.f / 512.f) + 1e-5f);
    const float4* gp = (const float4*)g;
    const float4* bp = (const float4*)b;
#pragma unroll
    for (int q = 0; q < 4; q++) {
        int c = lane + 32 * q;
        float4 gv = gp[c], bv = bp[c], o;
        o.x = (v[q].x - mean) * inv * gv.x + bv.x;
        o.y = (v[q].y - mean) * inv * gv.y + bv.y;
        o.z = (v[q].z - mean) * inv * gv.z + bv.z;
        o.w = (v[q].w - mean) * inv * gv.w + bv.w;
        if (do_relu) {
            o.x = fmaxf(o.x, 0.f); o.y = fmaxf(o.y, 0.f);
            o.z = fmaxf(o.z, 0.f); o.w = fmaxf(o.w, 0.f);
        }
        if (outf) ((float4*)(outf + (long long)warp * 512))[c] = o;
        if (outh) {
            __half2* hp = (__half2*)(outh + (long long)warp * 512);
            hp[c * 2 + 0] = __floats2half2_rn(o.x, o.y);
            hp[c * 2 + 1] = __floats2half2_rn(o.z, o.w);
        }
    }
}

// ---------------------------------------------------------------------------
// cos similarity + half GEMM inputs: hc = cos*prev, hs = (1-cos)*cur
// ---------------------------------------------------------------------------
__global__ __launch_bounds__(256) void cos_kernel(
    const float* __restrict__ spatial, float* __restrict__ cosv,
    __half* __restrict__ hc, __half* __restrict__ hs)
{
    int warp = (blockIdx.x * 256 + threadIdx.x) >> 5;
    int lane = threadIdx.x & 31;
    if (warp >= 50400) return;
    int i = warp % 50;
    int tq = (warp / 50) % 63;
    int b_ = warp / 3150;
    long long cur_off  = (((long long)b_ * 64 + tq + 1) * 50 + i) * 512;
    long long prev_off = (((long long)b_ * 64 + tq) * 50 + i) * 512;
    const float4* cp = (const float4*)(spatial + cur_off);
    const float4* pp = (const float4*)(spatial + prev_off);
    float4 cb[4], pb[4];
    float dt = 0.f, na = 0.f, nb = 0.f;
#pragma unroll
    for (int q = 0; q < 4; q++) {
        cb[q] = cp[lane + 32 * q];
        pb[q] = pp[lane + 32 * q];
        dt += cb[q].x * pb[q].x + cb[q].y * pb[q].y + cb[q].z * pb[q].z + cb[q].w * pb[q].w;
        na += cb[q].x * cb[q].x + cb[q].y * cb[q].y + cb[q].z * cb[q].z + cb[q].w * cb[q].w;
        nb += pb[q].x * pb[q].x + pb[q].y * pb[q].y + pb[q].z * pb[q].z + pb[q].w * pb[q].w;
    }
#pragma unroll
    for (int off = 16; off; off >>= 1) {
        dt += __shfl_xor_sync(0xffffffffu, dt, off);
        na += __shfl_xor_sync(0xffffffffu, na, off);
        nb += __shfl_xor_sync(0xffffffffu, nb, off);
    }
    float cv = dt / (fmaxf(sqrtf(na), 1e-8f) * fmaxf(sqrtf(nb), 1e-8f));
    if (lane == 0) cosv[warp] = cv;
    __half2* hcp = (__half2*)(hc + (long long)warp * 512);
    __half2* hsp = (__half2*)(hs + (long long)warp * 512);
    float w1 = 1.f - cv;
#pragma unroll
    for (int q = 0; q < 4; q++) {
        int c = lane + 32 * q;
        hcp[c * 2 + 0] = __floats2half2_rn(cv * pb[q].x, cv * pb[q].y);
        hcp[c * 2 + 1] = __floats2half2_rn(cv * pb[q].z, cv * pb[q].w);
        hsp[c * 2 + 0] = __floats2half2_rn(w1 * cb[q].x, w1 * cb[q].y);
        hsp[c * 2 + 1] = __floats2half2_rn(w1 * cb[q].z, w1 * cb[q].w);
    }
}

// ---------------------------------------------------------------------------
// Host launcher
// ---------------------------------------------------------------------------
extern "C" void kernel_launch(void* const* d_in, const int* in_sizes, int n_in,
                              void* d_out, int out_size)
{
    const float* visual = (const float*)d_in[0];
    const float* audio  = (const float*)d_in[1];
    const float* in_W   = (const float*)d_in[2];
    const float* in_b   = (const float*)d_in[3];
    const float* out_W  = (const float*)d_in[4];
    const float* out_b  = (const float*)d_in[5];

    float *node, *spatial, *t1, *t2, *attnb, *cosb;
    __half *hA, *hc, *hs, *ht3, *hnode, *wh;
    cudaGetSymbolAddress((void**)&node,    g_node);
    cudaGetSymbolAddress((void**)&spatial, g_spatial);
    cudaGetSymbolAddress((void**)&t1,      g_t1);
    cudaGetSymbolAddress((void**)&t2,      g_t2);
    cudaGetSymbolAddress((void**)&attnb,   g_attn);
    cudaGetSymbolAddress((void**)&cosb,    g_cos);
    cudaGetSymbolAddress((void**)&hA,      g_hA);
    cudaGetSymbolAddress((void**)&hc,      g_hc);
    cudaGetSymbolAddress((void**)&hs,      g_hs);
    cudaGetSymbolAddress((void**)&ht3,     g_ht3);
    cudaGetSymbolAddress((void**)&hnode,   g_hnode);
    cudaGetSymbolAddress((void**)&wh,      g_wh);

    // direct-output targets when d_out is large enough
    long long need = OUT_ELEMS + ATTN_ELEMS + COS_ELEMS;
    bool direct = ((long long)out_size >= need);
    float* attn_dst = direct ? (float*)d_out + OUT_ELEMS : attnb;
    float* cos_dst  = direct ? (float*)d_out + OUT_ELEMS + ATTN_ELEMS : cosb;

    cudaFuncSetAttribute(attn_kernel,
                         cudaFuncAttributeMaxDynamicSharedMemorySize, ATTN_SMEM_BYTES);
    cudaFuncSetAttribute(gemm_fp16,
                         cudaFuncAttributeMaxDynamicSharedMemorySize, GEMM_SMEM);

    wround8_kernel<<<2048, 256>>>(
        in_W, (const float*)d_in[9], (const float*)d_in[11], (const float*)d_in[13],
        (const float*)d_in[17], (const float*)d_in[19], (const float*)d_in[21], out_W,
        wh);

    concat_kernel<<<25600, 256>>>(visual, audio, hA);
    dim3 gAll(4, 400);
    dim3 gTmp(4, 394);
    gemm_fp16<<<gAll, 256, GEMM_SMEM>>>(hA, wh + 0 * 262144, in_b,
                                        nullptr, nullptr, node, hnode,
                                        51200, 0);

    for (int L = 0; L < 2; L++) {
        int base = 6 + L * 8;
        const float* edge = (const float*)d_in[base + 0];
        const float* lng  = (const float*)d_in[base + 1];
        const float* lnb  = (const float*)d_in[base + 2];
        const float* bc   = (const float*)d_in[base + 4];
        const float* bs   = (const float*)d_in[base + 6];
        const __half* wc  = wh + (long long)(1 + L * 3) * 262144;
        const __half* ws  = wh + (long long)(2 + L * 3) * 262144;
        const __half* wo  = wh + (long long)(3 + L * 3) * 262144;

        attn_kernel<<<1024, 256, ATTN_SMEM_BYTES>>>(
            hnode, edge, lng, lnb, spatial, (L == 1) ? attn_dst : nullptr);
        cos_kernel<<<6300, 256>>>(spatial, (L == 1) ? cos_dst : cosb, hc, hs);
        gemm_fp16<<<gTmp, 256, GEMM_SMEM>>>(hc, wc, bc, nullptr, nullptr,
                                            t1, nullptr, 50400, 1);
        gemm_fp16<<<gTmp, 256, GEMM_SMEM>>>(hs, ws, bs, t1, spatial,
                                            t2, nullptr, 50400, 2);
        ln_kernel<<<6400, 256>>>(t2, spatial, nullptr, ht3, lng, lnb, 51200, 0);
        // L==1: fp32 node no longer consumed afterwards -> skip its write
        gemm_fp16<<<gAll, 256, GEMM_SMEM>>>(ht3, wo, nullptr, node, nullptr,
                                            (L == 0) ? node : nullptr, hnode,
                                            51200, 3);
    }

    gemm_fp16<<<gAll, 256, GEMM_SMEM>>>(hnode, wh + 7LL * 262144, out_b,
                                        nullptr, nullptr, (float*)d_out,
                                        nullptr, 51200, 0);
}